// round 3
// baseline (speedup 1.0000x reference)
#include <cuda_runtime.h>
#include <cstdint>
#include <cstddef>

#define Bb   8
#define Nn   256
#define Mm   512
#define EXTm 768
#define Ee   1024
#define Hh   32
#define TN   16
#define SCALING 0.17677669529663687f
#define NEGINF  -3.402823466e38f

typedef unsigned long long u64;

__device__ __forceinline__ void ffma2(u64 &d, u64 a, u64 b) {
    asm("fma.rn.f32x2 %0, %1, %2, %0;" : "+l"(d) : "l"(a), "l"(b));
}
__device__ __forceinline__ u64 pkf(float x) {
    u64 r; asm("mov.b64 %0, {%1, %1};" : "=l"(r) : "f"(x)); return r;
}
__device__ __forceinline__ float2 upk(u64 v) {
    float2 f; asm("mov.b64 {%0, %1}, %2;" : "=f"(f.x), "=f"(f.y) : "l"(v)); return f;
}
__device__ __forceinline__ u64 d2u(double d) { return __double_as_longlong(d); }

// ---------------- scratch ----------------
__device__ float g_q [(size_t)Bb*Nn*Ee];
__device__ float g_k [(size_t)Bb*EXTm*Ee];
__device__ float g_v [(size_t)Bb*EXTm*Ee];
__device__ float g_ve[(size_t)Bb*EXTm*Ee];
__device__ float g_xo[(size_t)Bb*Nn*Ee];
__device__ float g_vec[(size_t)Bb*Nn*3*Ee];

// ================= FFMA2 SGEMM core: 128x64 tile, 256 thr, 8x4/thread =================
// C[r,j] = sum_k A[r,k] * W[j,k]; A row pointer given per-thread; result via functor-ish mode.
struct GemmCore {
    __device__ static void run(const float* __restrict__ arow,   // A row base for this thread's stage slot (+k offset added)
                               const float* __restrict__ brow,   // W row base for stage slot
                               u64 acc[4][4],
                               float As[16][128], float Bs[16][64],
                               int t)
    {
        const int tx = t & 15, ty = t >> 4;
        const int ia = t >> 1, ka = (t & 1) * 8;
        const int jb = t >> 2, kb = (t & 3) * 4;

        for (int kk = 0; kk < Ee; kk += 16) {
            float4 a0 = *(const float4*)(arow + kk);
            float4 a1 = *(const float4*)(arow + kk + 4);
            float4 b0 = *(const float4*)(brow + kk);
            __syncthreads();
            As[ka+0][ia] = a0.x; As[ka+1][ia] = a0.y; As[ka+2][ia] = a0.z; As[ka+3][ia] = a0.w;
            As[ka+4][ia] = a1.x; As[ka+5][ia] = a1.y; As[ka+6][ia] = a1.z; As[ka+7][ia] = a1.w;
            Bs[kb+0][jb] = b0.x; Bs[kb+1][jb] = b0.y; Bs[kb+2][jb] = b0.z; Bs[kb+3][jb] = b0.w;
            __syncthreads();
#pragma unroll
            for (int k = 0; k < 16; k++) {
                double2 A01 = *(const double2*)&As[k][ty*8];
                double2 A23 = *(const double2*)&As[k][ty*8 + 4];
                u64 ap[4] = { d2u(A01.x), d2u(A01.y), d2u(A23.x), d2u(A23.y) };
                float4 bv = *(const float4*)&Bs[k][tx*4];
                u64 bp[4] = { pkf(bv.x), pkf(bv.y), pkf(bv.z), pkf(bv.w) };
#pragma unroll
                for (int i = 0; i < 4; i++)
#pragma unroll
                    for (int j = 0; j < 4; j++)
                        ffma2(acc[i][j], ap[i], bp[j]);
            }
        }
    }
};

// ---- projections: grid (16,16,4); z selects Wq/Wk/Wv/Wve ----
__global__ void __launch_bounds__(256) proj_gemm(const float* __restrict__ x,
                                                 const float* __restrict__ Wq,
                                                 const float* __restrict__ Wk,
                                                 const float* __restrict__ Wv,
                                                 const float* __restrict__ Wve)
{
    __shared__ float As[16][128];
    __shared__ float Bs[16][64];
    const int t = threadIdx.x;
    const int row0 = blockIdx.y * 128;
    const int col0 = blockIdx.x * 64;
    const int w = blockIdx.z;
    const float* W = (w == 0) ? Wq : (w == 1) ? Wk : (w == 2) ? Wv : Wve;

    u64 acc[4][4];
#pragma unroll
    for (int i = 0; i < 4; i++)
#pragma unroll
        for (int j = 0; j < 4; j++) acc[i][j] = 0ull;

    const int ra = row0 + (t >> 1);
    const int b = ra >> 8, n = ra & 255;
    const float* arow = x + ((size_t)n * Bb + b) * Ee + (t & 1) * 8;
    const float* brow = W + (size_t)(col0 + (t >> 2)) * Ee + (t & 3) * 4;

    GemmCore::run(arow, brow, acc, As, Bs, t);

    const int tx = t & 15, ty = t >> 4;
#pragma unroll
    for (int i2 = 0; i2 < 4; i2++) {
        float2 c0 = upk(acc[i2][0]), c1 = upk(acc[i2][1]);
        float2 c2 = upk(acc[i2][2]), c3 = upk(acc[i2][3]);
        int r = row0 + ty*8 + i2*2;
        int c = col0 + tx*4;
        float4 v0 = make_float4(c0.x, c1.x, c2.x, c3.x);
        float4 v1 = make_float4(c0.y, c1.y, c2.y, c3.y);
        int rb0 = r >> 8, rn0 = r & 255;
        int rb1 = (r+1) >> 8, rn1 = (r+1) & 255;
        if (w == 0) {
            v0.x *= SCALING; v0.y *= SCALING; v0.z *= SCALING; v0.w *= SCALING;
            v1.x *= SCALING; v1.y *= SCALING; v1.z *= SCALING; v1.w *= SCALING;
            *(float4*)&g_q[(size_t)r*Ee + c]     = v0;
            *(float4*)&g_q[(size_t)(r+1)*Ee + c] = v1;
        } else {
            float* dst = (w == 1) ? g_k : (w == 2) ? g_v : g_ve;
            *(float4*)&dst[((size_t)rb0*EXTm + rn0)*Ee + c] = v0;
            *(float4*)&dst[((size_t)rb1*EXTm + rn1)*Ee + c] = v1;
        }
    }
}

// ---- output GEMMs: mode 4 (g_xo @ Woe^T), mode 5 (g_vec @ Wo^T) ----
__global__ void __launch_bounds__(256) out_gemm(const float* __restrict__ W,
                                                float* __restrict__ Cout, int mode)
{
    __shared__ float As[16][128];
    __shared__ float Bs[16][64];
    const int t = threadIdx.x;
    const int row0 = blockIdx.y * 128;
    const int col0 = blockIdx.x * 64;

    u64 acc[4][4];
#pragma unroll
    for (int i = 0; i < 4; i++)
#pragma unroll
        for (int j = 0; j < 4; j++) acc[i][j] = 0ull;

    const int ra = row0 + (t >> 1);
    const float* A = (mode == 4) ? g_xo : g_vec;
    const float* arow = A + (size_t)ra * Ee + (t & 1) * 8;
    const float* brow = W + (size_t)(col0 + (t >> 2)) * Ee + (t & 3) * 4;

    GemmCore::run(arow, brow, acc, As, Bs, t);

    const int tx = t & 15, ty = t >> 4;
#pragma unroll
    for (int i2 = 0; i2 < 4; i2++) {
        float2 c0 = upk(acc[i2][0]), c1 = upk(acc[i2][1]);
        float2 c2 = upk(acc[i2][2]), c3 = upk(acc[i2][3]);
        int r = row0 + ty*8 + i2*2;
        int c = col0 + tx*4;
        *(float4*)&Cout[(size_t)r*Ee + c]     = make_float4(c0.x, c1.x, c2.x, c3.x);
        *(float4*)&Cout[(size_t)(r+1)*Ee + c] = make_float4(c0.y, c1.y, c2.y, c3.y);
    }
}

// ---------------- gather ----------------
__global__ void __launch_bounds__(256) gather_kernel(const int* __restrict__ idx)
{
    int bm = blockIdx.x;
    int b = bm >> 9, m = bm & 511;
    int s = idx[bm];
    size_t so = ((size_t)b*EXTm + s)      * Ee;
    size_t dd = ((size_t)b*EXTm + Nn + m) * Ee;
    int e = threadIdx.x * 4;
    *(float4*)&g_k [dd+e] = *(const float4*)&g_k [so+e];
    *(float4*)&g_v [dd+e] = *(const float4*)&g_v [so+e];
    *(float4*)&g_ve[dd+e] = *(const float4*)&g_ve[so+e];
}

// ---------------- attention ----------------
struct AttnSmem {
    float4 pdt4[TN][64];
    float  Vt [64][32];
    float  VEt[64][32];
    float  s  [TN][769];
    float  sq [TN][32];
    float  posn[TN][4];
    unsigned int spm[TN];
};

__global__ void __launch_bounds__(512, 2) attn_kernel(
    const float* __restrict__ pos, const float* __restrict__ epos,
    const float* __restrict__ bias,
    const unsigned char* __restrict__ pmask, const unsigned char* __restrict__ emask)
{
    extern __shared__ char smraw[];
    AttnSmem& sm = *reinterpret_cast<AttnSmem*>(smraw);
    const int t  = threadIdx.x;
    const int nt = blockIdx.x & 15;
    const int bh = blockIdx.x >> 4;
    const int h  = bh & 31, b = bh >> 5;
    const int n0 = nt * TN;

    {
        int ni = t >> 5, d = t & 31;
        sm.sq[ni][d] = g_q[((size_t)(b*Nn + n0 + ni))*Ee + h*32 + d];
        if (d == 0) sm.spm[ni] = pmask[b*Nn + n0 + ni];
        if (d < 3)  sm.posn[ni][d] = pos[((size_t)b*Nn + n0 + ni)*3 + d];
    }
    __syncthreads();

    // -------- scores (FFMA2) --------
    for (int m = t; m < EXTm; m += 512) {
        unsigned int fm = (m < Nn) ? pmask[b*Nn + m] : emask[b*Mm + m - Nn];
        const double2* kr = (const double2*)(g_k + ((size_t)b*EXTm + m)*Ee + h*32);
        u64 kd[16];
#pragma unroll
        for (int i = 0; i < 8; i++) {
            double2 kk = kr[i];
            kd[2*i]   = d2u(kk.x);
            kd[2*i+1] = d2u(kk.y);
        }
        const float* brow = bias + (((size_t)(b*Hh + h))*Nn + n0)*EXTm + m;
#pragma unroll
        for (int ni = 0; ni < TN; ni++) {
            const u64* q2 = (const u64*)sm.sq[ni];
            u64 acc2 = 0ull;
#pragma unroll
            for (int i = 0; i < 16; i++) ffma2(acc2, q2[i], kd[i]);
            float2 hs = upk(acc2);
            float acc = hs.x + hs.y + brow[(size_t)ni * EXTm];
            if (fm | sm.spm[ni]) acc = NEGINF;
            sm.s[ni][m] = acc;
        }
    }
    __syncthreads();

    // -------- softmax: one warp per query row --------
    {
        int ni = t >> 5, lane = t & 31;
        float lm = NEGINF;
#pragma unroll
        for (int i = 0; i < 24; i++) lm = fmaxf(lm, sm.s[ni][lane + i*32]);
#pragma unroll
        for (int o = 16; o; o >>= 1) lm = fmaxf(lm, __shfl_xor_sync(0xffffffffu, lm, o));
        float ls = 0.f;
#pragma unroll
        for (int i = 0; i < 24; i++) {
            float p = __expf(sm.s[ni][lane + i*32] - lm);
            sm.s[ni][lane + i*32] = p;
            ls += p;
        }
#pragma unroll
        for (int o = 16; o; o >>= 1) ls += __shfl_xor_sync(0xffffffffu, ls, o);
        float inv = 1.f / ls;
#pragma unroll
        for (int i = 0; i < 24; i++) sm.s[ni][lane + i*32] *= inv;
    }

    // -------- output accumulation (FFMA2) --------
    const int dq  = t & 7;
    const int ni2 = (t >> 3) & 15;
    const int g   = t >> 7;
    u64 A00=0, A01=0, A10=0, A11=0, A20=0, A21=0, A30=0, A31=0;

    for (int m0 = 0; m0 < EXTm; m0 += 64) {
        __syncthreads();
        {
            int ml = t >> 3, d4 = (t & 7) * 4;
            *(float4*)&sm.Vt [ml][d4] = *(const float4*)(g_v  + ((size_t)b*EXTm + m0 + ml)*Ee + h*32 + d4);
            *(float4*)&sm.VEt[ml][d4] = *(const float4*)(g_ve + ((size_t)b*EXTm + m0 + ml)*Ee + h*32 + d4);
        }
        for (int i = t; i < TN*64; i += 512) {
            int nii = i >> 6, ml = i & 63;
            int m = m0 + ml;
            float ax, ay, az; unsigned int fm;
            if (m < Nn) {
                const float* pp = pos + ((size_t)b*Nn + m)*3;
                ax = pp[0]; ay = pp[1]; az = pp[2];
                fm = pmask[b*Nn + m];
            } else {
                const float* pp = epos + ((size_t)b*Mm + (m - Nn))*3;
                ax = pp[0]; ay = pp[1]; az = pp[2];
                fm = emask[b*Mm + m - Nn];
            }
            float dx = sm.posn[nii][0] - ax;
            float dy = sm.posn[nii][1] - ay;
            float dz = sm.posn[nii][2] - az;
            float dist = sqrtf(dx*dx + dy*dy + dz*dz);
            if (sm.spm[nii] | fm) dist = 1e6f;
            float f = sm.s[nii][m] / (dist + 1.f);
            if (sm.spm[nii]) f = 0.f;
            sm.pdt4[nii][ml] = make_float4(dx*f, dy*f, dz*f, 0.f);
        }
        __syncthreads();
#pragma unroll
        for (int mi = 0; mi < 16; mi++) {
            int ml = g + mi*4;
            const u64* vv2 = (const u64*)&sm.Vt [ml][dq*4];
            const u64* ve2 = (const u64*)&sm.VEt[ml][dq*4];
            u64 v0 = vv2[0], v1 = vv2[1];
            u64 e0 = ve2[0], e1 = ve2[1];
            float p  = sm.s[ni2][m0 + ml];
            float4 pd = sm.pdt4[ni2][ml];
            u64 bp = pkf(p), bx = pkf(pd.x), by = pkf(pd.y), bz = pkf(pd.z);
            ffma2(A00, e0, bp); ffma2(A01, e1, bp);
            ffma2(A10, v0, bx); ffma2(A11, v1, bx);
            ffma2(A20, v0, by); ffma2(A21, v1, by);
            ffma2(A30, v0, bz); ffma2(A31, v1, bz);
        }
    }

    float2 p00 = upk(A00), p01 = upk(A01);
    float2 p10 = upk(A10), p11 = upk(A11);
    float2 p20 = upk(A20), p21 = upk(A21);
    float2 p30 = upk(A30), p31 = upk(A31);
    float4 a0 = make_float4(p00.x, p00.y, p01.x, p01.y);
    float4 a1 = make_float4(p10.x, p10.y, p11.x, p11.y);
    float4 a2 = make_float4(p20.x, p20.y, p21.x, p21.y);
    float4 a3 = make_float4(p30.x, p30.y, p31.x, p31.y);

    __syncthreads();
    float4* red = (float4*)&sm.pdt4[0][0];
    const size_t rowb = (size_t)(b*Nn + n0 + ni2);
    const int    coff = h*32 + dq*4;

    red[t] = a0; __syncthreads();
    if (g == 0) {
        float4 r0 = red[t], r1 = red[t+128], r2 = red[t+256], r3 = red[t+384];
        r0.x += r1.x + r2.x + r3.x; r0.y += r1.y + r2.y + r3.y;
        r0.z += r1.z + r2.z + r3.z; r0.w += r1.w + r2.w + r3.w;
        *(float4*)&g_xo[rowb*Ee + coff] = r0;
    }
    __syncthreads();
    red[t] = a1; __syncthreads();
    if (g == 0) {
        float4 r0 = red[t], r1 = red[t+128], r2 = red[t+256], r3 = red[t+384];
        r0.x += r1.x + r2.x + r3.x; r0.y += r1.y + r2.y + r3.y;
        r0.z += r1.z + r2.z + r3.z; r0.w += r1.w + r2.w + r3.w;
        *(float4*)&g_vec[(rowb*3 + 0)*Ee + coff] = r0;
    }
    __syncthreads();
    red[t] = a2; __syncthreads();
    if (g == 0) {
        float4 r0 = red[t], r1 = red[t+128], r2 = red[t+256], r3 = red[t+384];
        r0.x += r1.x + r2.x + r3.x; r0.y += r1.y + r2.y + r3.y;
        r0.z += r1.z + r2.z + r3.z; r0.w += r1.w + r2.w + r3.w;
        *(float4*)&g_vec[(rowb*3 + 1)*Ee + coff] = r0;
    }
    __syncthreads();
    red[t] = a3; __syncthreads();
    if (g == 0) {
        float4 r0 = red[t], r1 = red[t+128], r2 = red[t+256], r3 = red[t+384];
        r0.x += r1.x + r2.x + r3.x; r0.y += r1.y + r2.y + r3.y;
        r0.z += r1.z + r2.z + r3.z; r0.w += r1.w + r2.w + r3.w;
        *(float4*)&g_vec[(rowb*3 + 2)*Ee + coff] = r0;
    }
}

// ---------------- host entry ----------------
extern "C" void kernel_launch(void* const* d_in, const int* in_sizes, int n_in,
                              void* d_out, int out_size)
{
    const float* x    = (const float*)d_in[0];
    const float* pos  = (const float*)d_in[1];
    const float* epos = (const float*)d_in[2];
    const float* bias = (const float*)d_in[3];
    const unsigned char* pmask = (const unsigned char*)d_in[4];
    const unsigned char* emask = (const unsigned char*)d_in[5];
    const int*   idx  = (const int*)d_in[6];
    const float* Wq   = (const float*)d_in[7];
    const float* Wk   = (const float*)d_in[8];
    const float* Wv   = (const float*)d_in[9];
    const float* Wve  = (const float*)d_in[10];
    const float* Wo   = (const float*)d_in[11];
    const float* Woe  = (const float*)d_in[12];
    float* out = (float*)d_out;

    cudaFuncSetAttribute(attn_kernel, cudaFuncAttributeMaxDynamicSharedMemorySize,
                         (int)sizeof(AttnSmem));

    proj_gemm<<<dim3(16, 16, 4), 256>>>(x, Wq, Wk, Wv, Wve);

    gather_kernel<<<Bb*Mm, 256>>>(idx);

    attn_kernel<<<Bb*Hh*(Nn/TN), 512, sizeof(AttnSmem)>>>(pos, epos, bias, pmask, emask);

    out_gemm<<<dim3(16, 16, 1), 256>>>(Woe, out, 4);
    out_gemm<<<dim3(16, 48, 1), 256>>>(Wo, out + (size_t)Bb*Nn*Ee, 5);
}

// round 5
// speedup vs baseline: 2.1445x; 2.1445x over previous
#include <cuda_runtime.h>
#include <cuda_bf16.h>
#include <cstdint>
#include <cstddef>

typedef unsigned int u32;
typedef unsigned long long u64;

#define Bb   8
#define Nn   256
#define Mm   512
#define EXTm 768
#define Ee   1024
#define Hh   32
#define TN   16
#define SCALING 0.17677669529663687f
#define NEGINF  -3.402823466e38f

// ---------------- scratch ----------------
__device__ float g_q [(size_t)Bb*Nn*Ee];
__device__ float g_k [(size_t)Bb*EXTm*Ee];
__device__ float g_v [(size_t)Bb*EXTm*Ee];
__device__ float g_ve[(size_t)Bb*EXTm*Ee];
__device__ float g_xo[(size_t)Bb*Nn*Ee];
__device__ float g_vec[(size_t)Bb*Nn*3*Ee];
__device__ __nv_bfloat16 g_ah[(size_t)8192*Ee];   // A hi
__device__ __nv_bfloat16 g_al[(size_t)8192*Ee];   // A lo
__device__ __nv_bfloat16 g_wh[(size_t)6*Ee*Ee];   // W hi: Wq,Wk,Wv,Wve,Woe,Wo
__device__ __nv_bfloat16 g_wl[(size_t)6*Ee*Ee];   // W lo

// ---------------- helpers ----------------
__device__ __forceinline__ u32 smem_u32(const void* p){
    u32 a; asm("{ .reg .u64 t; cvta.to.shared.u64 t, %1; cvt.u32.u64 %0, t; }" : "=r"(a) : "l"(p)); return a;
}
__device__ __forceinline__ void cpasync16(u32 dst, const void* src){
    asm volatile("cp.async.ca.shared.global [%0], [%1], 16;" :: "r"(dst), "l"(src) : "memory");
}
__device__ __forceinline__ void ldsm4(u32 r[4], u32 addr){
    asm volatile("ldmatrix.sync.aligned.m8n8.x4.shared.b16 {%0,%1,%2,%3}, [%4];"
                 : "=r"(r[0]), "=r"(r[1]), "=r"(r[2]), "=r"(r[3]) : "r"(addr));
}
__device__ __forceinline__ void mma16816(float c[4], const u32 a[4], u32 b0, u32 b1){
    asm volatile("mma.sync.aligned.m16n8k16.row.col.f32.bf16.bf16.f32 "
                 "{%0,%1,%2,%3}, {%4,%5,%6,%7}, {%8,%9}, {%0,%1,%2,%3};"
                 : "+f"(c[0]), "+f"(c[1]), "+f"(c[2]), "+f"(c[3])
                 : "r"(a[0]), "r"(a[1]), "r"(a[2]), "r"(a[3]), "r"(b0), "r"(b1));
}

// ---------------- fp32 -> bf16 hi/lo split ----------------
__device__ __forceinline__ void split_store(size_t off, float4 v,
                                            __nv_bfloat16* dh, __nv_bfloat16* dl){
    __nv_bfloat16 h0 = __float2bfloat16(v.x), h1 = __float2bfloat16(v.y);
    __nv_bfloat16 h2 = __float2bfloat16(v.z), h3 = __float2bfloat16(v.w);
    __nv_bfloat16 l0 = __float2bfloat16(v.x - __bfloat162float(h0));
    __nv_bfloat16 l1 = __float2bfloat16(v.y - __bfloat162float(h1));
    __nv_bfloat16 l2 = __float2bfloat16(v.z - __bfloat162float(h2));
    __nv_bfloat16 l3 = __float2bfloat16(v.w - __bfloat162float(h3));
    *(__nv_bfloat162*)&dh[off]   = __halves2bfloat162(h0, h1);
    *(__nv_bfloat162*)&dh[off+2] = __halves2bfloat162(h2, h3);
    *(__nv_bfloat162*)&dl[off]   = __halves2bfloat162(l0, l1);
    *(__nv_bfloat162*)&dl[off+2] = __halves2bfloat162(l2, l3);
}

__global__ void __launch_bounds__(256) cvt_w(const float* __restrict__ Wq, const float* __restrict__ Wk,
                                             const float* __restrict__ Wv, const float* __restrict__ Wve,
                                             const float* __restrict__ Woe, const float* __restrict__ Wo)
{
    int w = blockIdx.y;
    const float* W = (w==0)?Wq:(w==1)?Wk:(w==2)?Wv:(w==3)?Wve:(w==4)?Woe:Wo;
    size_t i = ((size_t)blockIdx.x*256 + threadIdx.x)*4;
    float4 v = *(const float4*)(W + i);
    split_store((size_t)w*Ee*Ee + i, v, g_wh, g_wl);
}

__global__ void __launch_bounds__(256) cvt_x(const float* __restrict__ x)
{
    int r = blockIdx.x;                        // 0..2047 = b*256+n
    int b = r >> 8, n = r & 255;
    int e = threadIdx.x * 4;
    float4 v = *(const float4*)(x + ((size_t)n*Bb + b)*Ee + e);
    split_store((size_t)r*Ee + e, v, g_ah, g_al);
}

__global__ void __launch_bounds__(256) cvt_o()
{
    int r = blockIdx.x;                        // 0..8191
    const float* src = (r < 2048) ? (g_xo + (size_t)r*Ee)
                                  : (g_vec + (size_t)(r-2048)*Ee);
    int e = threadIdx.x * 4;
    float4 v = *(const float4*)(src + e);
    split_store((size_t)r*Ee + e, v, g_ah, g_al);
}

// ========== bf16-split mma.sync GEMM: 128x128 tile, 8 warps, cp.async 2-stage ==========
// mode 0: units by blockIdx.z (0=q scaled,1=k,2=v,3=ve); mode 4: xo@Woe; mode 5: vec@Wo
#define ST_ROW   40                         // smem row stride in bf16 (80B): ldmatrix conflict-free
#define MAT_SZ   (128*ST_ROW*2)             // 10240 B per matrix
#define STAGE_SZ (4*MAT_SZ)                 // Ah,Al,Bh,Bl = 40960 B
#define MM_SMEM  (2*STAGE_SZ)               // 81920 B

__global__ void __launch_bounds__(256) mm_mma(float* __restrict__ Cout, int mode)
{
    extern __shared__ __align__(16) char smraw[];
    const u32 smBase = smem_u32(smraw);
    const int t = threadIdx.x, wid = t >> 5, lid = t & 31;
    const int wm = wid >> 2, wn = wid & 3;             // 2x4 warp grid
    const int col0 = blockIdx.x * 128;
    const int row0 = blockIdx.y * 128;
    const int unit = (mode == 0) ? (int)blockIdx.z : mode;
    const int arow0 = (unit == 5) ? (2048 + row0) : row0;

    const __nv_bfloat16* srcs[4] = {
        g_ah + (size_t)arow0*Ee,
        g_al + (size_t)arow0*Ee,
        g_wh + (size_t)unit*Ee*Ee + (size_t)col0*Ee,
        g_wl + (size_t)unit*Ee*Ee + (size_t)col0*Ee
    };

    float acc[4][4][4];
#pragma unroll
    for (int i = 0; i < 4; i++)
#pragma unroll
        for (int j = 0; j < 4; j++)
#pragma unroll
            for (int q = 0; q < 4; q++) acc[i][j][q] = 0.f;

    // per-thread cp.async mapping (8 x 16B per chunk)
    int cp_mat[8], cp_row[8], cp_q[8];
#pragma unroll
    for (int jj = 0; jj < 8; jj++) {
        int id = t + jj*256;
        cp_mat[jj] = id >> 9; int rem = id & 511;
        cp_row[jj] = rem >> 2; cp_q[jj] = rem & 3;
    }

#define ISSUE(kc, stage)                                                          \
    {   int k0 = (kc)*32;                                                         \
        u32 dB = smBase + (stage)*STAGE_SZ;                                       \
        _Pragma("unroll")                                                         \
        for (int jj = 0; jj < 8; jj++) {                                          \
            const __nv_bfloat16* s = srcs[cp_mat[jj]] + (size_t)cp_row[jj]*Ee + k0 + cp_q[jj]*8; \
            cpasync16(dB + cp_mat[jj]*MAT_SZ + cp_row[jj]*(ST_ROW*2) + cp_q[jj]*16, s); \
        }                                                                         \
        asm volatile("cp.async.commit_group;" ::: "memory");                      \
    }

    ISSUE(0, 0);

    const u32 aoff = (u32)(((lid >> 3) & 1) * 8 + (lid & 7));   // row-in-16 for ldmatrix lanes
    const u32 kbl  = (u32)(((lid >> 4) & 1) * 16);              // k-half byte offset

    for (int kc = 0; kc < 32; kc++) {
        int stage = kc & 1;
        if (kc < 31) ISSUE(kc + 1, stage ^ 1);
        if (kc < 31) asm volatile("cp.async.wait_group 1;" ::: "memory");
        else         asm volatile("cp.async.wait_group 0;" ::: "memory");
        __syncthreads();

        u32 base = smBase + stage*STAGE_SZ;
#pragma unroll
        for (int ks = 0; ks < 2; ks++) {
            u32 kb = kbl + ks*32;
            u32 ah[4][4], al[4][4];
            u32 bh0[4], bh1[4], bl0[4], bl1[4];
#pragma unroll
            for (int im = 0; im < 4; im++) {
                u32 row = (u32)(wm*64 + im*16) + aoff;
                ldsm4(ah[im], base + 0*MAT_SZ + row*(ST_ROW*2) + kb);
                ldsm4(al[im], base + 1*MAT_SZ + row*(ST_ROW*2) + kb);
            }
#pragma unroll
            for (int jn = 0; jn < 2; jn++) {
                u32 row = (u32)(wn*32 + jn*16) + aoff;
                u32 rh[4], rl[4];
                ldsm4(rh, base + 2*MAT_SZ + row*(ST_ROW*2) + kb);
                ldsm4(rl, base + 3*MAT_SZ + row*(ST_ROW*2) + kb);
                bh0[jn*2] = rh[0]; bh1[jn*2] = rh[2]; bh0[jn*2+1] = rh[1]; bh1[jn*2+1] = rh[3];
                bl0[jn*2] = rl[0]; bl1[jn*2] = rl[2]; bl0[jn*2+1] = rl[1]; bl1[jn*2+1] = rl[3];
            }
#pragma unroll
            for (int im = 0; im < 4; im++)
#pragma unroll
                for (int n8 = 0; n8 < 4; n8++) {
                    mma16816(acc[im][n8], ah[im], bh0[n8], bh1[n8]);
                    mma16816(acc[im][n8], al[im], bh0[n8], bh1[n8]);
                    mma16816(acc[im][n8], ah[im], bl0[n8], bl1[n8]);
                }
        }
        __syncthreads();
    }

    // -------- epilogue --------
    const int gid = lid >> 2, tig = lid & 3;
#pragma unroll
    for (int im = 0; im < 4; im++) {
#pragma unroll
        for (int n8 = 0; n8 < 4; n8++) {
            int c = col0 + wn*32 + n8*8 + tig*2;
            int r0 = row0 + wm*64 + im*16 + gid;
            int r1 = r0 + 8;
            float2 v0 = make_float2(acc[im][n8][0], acc[im][n8][1]);
            float2 v1 = make_float2(acc[im][n8][2], acc[im][n8][3]);
            if (unit == 0) {
                v0.x *= SCALING; v0.y *= SCALING; v1.x *= SCALING; v1.y *= SCALING;
                *(float2*)&g_q[(size_t)r0*Ee + c] = v0;
                *(float2*)&g_q[(size_t)r1*Ee + c] = v1;
            } else if (unit < 4) {
                float* dst = (unit == 1) ? g_k : (unit == 2) ? g_v : g_ve;
                *(float2*)&dst[((size_t)(r0 >> 8)*EXTm + (r0 & 255))*Ee + c] = v0;
                *(float2*)&dst[((size_t)(r1 >> 8)*EXTm + (r1 & 255))*Ee + c] = v1;
            } else {
                *(float2*)&Cout[(size_t)r0*Ee + c] = v0;
                *(float2*)&Cout[(size_t)r1*Ee + c] = v1;
            }
        }
    }
}

// ---------------- gather ----------------
__global__ void __launch_bounds__(256) gather_kernel(const int* __restrict__ idx)
{
    int bm = blockIdx.x;
    int b = bm >> 9, m = bm & 511;
    int s = idx[bm];
    size_t so = ((size_t)b*EXTm + s)      * Ee;
    size_t dd = ((size_t)b*EXTm + Nn + m) * Ee;
    int e = threadIdx.x * 4;
    *(float4*)&g_k [dd+e] = *(const float4*)&g_k [so+e];
    *(float4*)&g_v [dd+e] = *(const float4*)&g_v [so+e];
    *(float4*)&g_ve[dd+e] = *(const float4*)&g_ve[so+e];
}

// ---------------- attention (proven scalar version) ----------------
struct AttnSmem {
    float4 pdt4[TN][64];
    float  Vt [64][32];
    float  VEt[64][32];
    float  s  [TN][769];
    float  sq [TN][32];
    float  posn[TN][4];
    unsigned int spm[TN];
};

__global__ void __launch_bounds__(512, 2) attn_kernel(
    const float* __restrict__ pos, const float* __restrict__ epos,
    const float* __restrict__ bias,
    const unsigned char* __restrict__ pmask, const unsigned char* __restrict__ emask)
{
    extern __shared__ char smraw[];
    AttnSmem& sm = *reinterpret_cast<AttnSmem*>(smraw);
    const int t  = threadIdx.x;
    const int nt = blockIdx.x & 15;
    const int bh = blockIdx.x >> 4;
    const int h  = bh & 31, b = bh >> 5;
    const int n0 = nt * TN;

    {
        int ni = t >> 5, d = t & 31;
        sm.sq[ni][d] = g_q[((size_t)(b*Nn + n0 + ni))*Ee + h*32 + d];
        if (d == 0) sm.spm[ni] = pmask[b*Nn + n0 + ni];
        if (d < 3)  sm.posn[ni][d] = pos[((size_t)b*Nn + n0 + ni)*3 + d];
    }
    __syncthreads();

    for (int m = t; m < EXTm; m += 512) {
        unsigned int fm = (m < Nn) ? pmask[b*Nn + m] : emask[b*Mm + m - Nn];
        const float4* kr = (const float4*)(g_k + ((size_t)b*EXTm + m)*Ee + h*32);
        float4 kd[8];
#pragma unroll
        for (int i = 0; i < 8; i++) kd[i] = kr[i];
        const float* brow = bias + (((size_t)(b*Hh + h))*Nn + n0)*EXTm + m;
#pragma unroll
        for (int ni = 0; ni < TN; ni++) {
            const float4* q4 = (const float4*)sm.sq[ni];
            float acc = 0.f;
#pragma unroll
            for (int i = 0; i < 8; i++) {
                float4 qv = q4[i];
                acc = fmaf(qv.x, kd[i].x, acc);
                acc = fmaf(qv.y, kd[i].y, acc);
                acc = fmaf(qv.z, kd[i].z, acc);
                acc = fmaf(qv.w, kd[i].w, acc);
            }
            acc += brow[(size_t)ni * EXTm];
            if (fm | sm.spm[ni]) acc = NEGINF;
            sm.s[ni][m] = acc;
        }
    }
    __syncthreads();

    {
        int ni = t >> 5, lane = t & 31;
        float lm = NEGINF;
#pragma unroll
        for (int i = 0; i < 24; i++) lm = fmaxf(lm, sm.s[ni][lane + i*32]);
#pragma unroll
        for (int o = 16; o; o >>= 1) lm = fmaxf(lm, __shfl_xor_sync(0xffffffffu, lm, o));
        float ls = 0.f;
#pragma unroll
        for (int i = 0; i < 24; i++) {
            float p = __expf(sm.s[ni][lane + i*32] - lm);
            sm.s[ni][lane + i*32] = p;
            ls += p;
        }
#pragma unroll
        for (int o = 16; o; o >>= 1) ls += __shfl_xor_sync(0xffffffffu, ls, o);
        float inv = 1.f / ls;
#pragma unroll
        for (int i = 0; i < 24; i++) sm.s[ni][lane + i*32] *= inv;
    }

    const int dq  = t & 7;
    const int ni2 = (t >> 3) & 15;
    const int g   = t >> 7;
    float4 a0 = make_float4(0,0,0,0), a1 = a0, a2 = a0, a3 = a0;

    for (int m0 = 0; m0 < EXTm; m0 += 64) {
        __syncthreads();
        {
            int ml = t >> 3, d4 = (t & 7) * 4;
            *(float4*)&sm.Vt [ml][d4] = *(const float4*)(g_v  + ((size_t)b*EXTm + m0 + ml)*Ee + h*32 + d4);
            *(float4*)&sm.VEt[ml][d4] = *(const float4*)(g_ve + ((size_t)b*EXTm + m0 + ml)*Ee + h*32 + d4);
        }
        for (int i = t; i < TN*64; i += 512) {
            int nii = i >> 6, ml = i & 63;
            int m = m0 + ml;
            float ax, ay, az; unsigned int fm;
            if (m < Nn) {
                const float* pp = pos + ((size_t)b*Nn + m)*3;
                ax = pp[0]; ay = pp[1]; az = pp[2];
                fm = pmask[b*Nn + m];
            } else {
                const float* pp = epos + ((size_t)b*Mm + (m - Nn))*3;
                ax = pp[0]; ay = pp[1]; az = pp[2];
                fm = emask[b*Mm + m - Nn];
            }
            float dx = sm.posn[nii][0] - ax;
            float dy = sm.posn[nii][1] - ay;
            float dz = sm.posn[nii][2] - az;
            float dist = sqrtf(dx*dx + dy*dy + dz*dz);
            if (sm.spm[nii] | fm) dist = 1e6f;
            float f = sm.s[nii][m] / (dist + 1.f);
            if (sm.spm[nii]) f = 0.f;
            sm.pdt4[nii][ml] = make_float4(dx*f, dy*f, dz*f, 0.f);
        }
        __syncthreads();
#pragma unroll
        for (int mi = 0; mi < 16; mi++) {
            int ml = g + mi*4;
            float4 vv  = *(const float4*)&sm.Vt [ml][dq*4];
            float4 vev = *(const float4*)&sm.VEt[ml][dq*4];
            float  p   = sm.s[ni2][m0 + ml];
            float4 pd  = sm.pdt4[ni2][ml];
            a0.x = fmaf(p, vev.x, a0.x); a0.y = fmaf(p, vev.y, a0.y);
            a0.z = fmaf(p, vev.z, a0.z); a0.w = fmaf(p, vev.w, a0.w);
            a1.x = fmaf(pd.x, vv.x, a1.x); a1.y = fmaf(pd.x, vv.y, a1.y);
            a1.z = fmaf(pd.x, vv.z, a1.z); a1.w = fmaf(pd.x, vv.w, a1.w);
            a2.x = fmaf(pd.y, vv.x, a2.x); a2.y = fmaf(pd.y, vv.y, a2.y);
            a2.z = fmaf(pd.y, vv.z, a2.z); a2.w = fmaf(pd.y, vv.w, a2.w);
            a3.x = fmaf(pd.z, vv.x, a3.x); a3.y = fmaf(pd.z, vv.y, a3.y);
            a3.z = fmaf(pd.z, vv.z, a3.z); a3.w = fmaf(pd.z, vv.w, a3.w);
        }
    }

    __syncthreads();
    float4* red = (float4*)&sm.pdt4[0][0];
    const size_t rowb = (size_t)(b*Nn + n0 + ni2);
    const int    coff = h*32 + dq*4;

    red[t] = a0; __syncthreads();
    if (g == 0) {
        float4 r0 = red[t], r1 = red[t+128], r2 = red[t+256], r3 = red[t+384];
        r0.x += r1.x + r2.x + r3.x; r0.y += r1.y + r2.y + r3.y;
        r0.z += r1.z + r2.z + r3.z; r0.w += r1.w + r2.w + r3.w;
        *(float4*)&g_xo[rowb*Ee + coff] = r0;
    }
    __syncthreads();
    red[t] = a1; __syncthreads();
    if (g == 0) {
        float4 r0 = red[t], r1 = red[t+128], r2 = red[t+256], r3 = red[t+384];
        r0.x += r1.x + r2.x + r3.x; r0.y += r1.y + r2.y + r3.y;
        r0.z += r1.z + r2.z + r3.z; r0.w += r1.w + r2.w + r3.w;
        *(float4*)&g_vec[(rowb*3 + 0)*Ee + coff] = r0;
    }
    __syncthreads();
    red[t] = a2; __syncthreads();
    if (g == 0) {
        float4 r0 = red[t], r1 = red[t+128], r2 = red[t+256], r3 = red[t+384];
        r0.x += r1.x + r2.x + r3.x; r0.y += r1.y + r2.y + r3.y;
        r0.z += r1.z + r2.z + r3.z; r0.w += r1.w + r2.w + r3.w;
        *(float4*)&g_vec[(rowb*3 + 1)*Ee + coff] = r0;
    }
    __syncthreads();
    red[t] = a3; __syncthreads();
    if (g == 0) {
        float4 r0 = red[t], r1 = red[t+128], r2 = red[t+256], r3 = red[t+384];
        r0.x += r1.x + r2.x + r3.x; r0.y += r1.y + r2.y + r3.y;
        r0.z += r1.z + r2.z + r3.z; r0.w += r1.w + r2.w + r3.w;
        *(float4*)&g_vec[(rowb*3 + 2)*Ee + coff] = r0;
    }
}

// ---------------- host entry ----------------
extern "C" void kernel_launch(void* const* d_in, const int* in_sizes, int n_in,
                              void* d_out, int out_size)
{
    const float* x    = (const float*)d_in[0];
    const float* pos  = (const float*)d_in[1];
    const float* epos = (const float*)d_in[2];
    const float* bias = (const float*)d_in[3];
    const unsigned char* pmask = (const unsigned char*)d_in[4];
    const unsigned char* emask = (const unsigned char*)d_in[5];
    const int*   idx  = (const int*)d_in[6];
    const float* Wq   = (const float*)d_in[7];
    const float* Wk   = (const float*)d_in[8];
    const float* Wv   = (const float*)d_in[9];
    const float* Wve  = (const float*)d_in[10];
    const float* Wo   = (const float*)d_in[11];
    const float* Woe  = (const float*)d_in[12];
    float* out = (float*)d_out;

    cudaFuncSetAttribute(mm_mma, cudaFuncAttributeMaxDynamicSharedMemorySize, MM_SMEM);
    cudaFuncSetAttribute(attn_kernel, cudaFuncAttributeMaxDynamicSharedMemorySize,
                         (int)sizeof(AttnSmem));

    cvt_w<<<dim3(1024, 6), 256>>>(Wq, Wk, Wv, Wve, Woe, Wo);
    cvt_x<<<2048, 256>>>(x);

    mm_mma<<<dim3(8, 16, 4), 256, MM_SMEM>>>(nullptr, 0);    // q,k,v,ve projections

    gather_kernel<<<Bb*Mm, 256>>>(idx);

    attn_kernel<<<Bb*Hh*(Nn/TN), 512, sizeof(AttnSmem)>>>(pos, epos, bias, pmask, emask);

    cvt_o<<<8192, 256>>>();

    mm_mma<<<dim3(8, 16, 1), 256, MM_SMEM>>>(out, 4);                       // xo @ Woe^T
    mm_mma<<<dim3(8, 48, 1), 256, MM_SMEM>>>(out + (size_t)2048*Ee, 5);     // vec @ Wo^T
}

// round 7
// speedup vs baseline: 2.8784x; 1.3422x over previous
#include <cuda_runtime.h>
#include <cuda_bf16.h>
#include <cstdint>
#include <cstddef>

typedef unsigned int u32;
typedef unsigned long long u64;

#define Bb   8
#define Nn   256
#define Mm   512
#define EXTm 768
#define Ee   1024
#define Hh   32
#define SCALING 0.17677669529663687f
#define NEGINF  -3.402823466e38f

// ---------------- scratch ----------------
__device__ float g_xo[(size_t)Bb*Nn*Ee];
__device__ float g_vec[(size_t)Bb*Nn*3*Ee];
__device__ __nv_bfloat16 g_ah[(size_t)8192*Ee];
__device__ __nv_bfloat16 g_al[(size_t)8192*Ee];
__device__ __nv_bfloat16 g_wh[(size_t)6*Ee*Ee];
__device__ __nv_bfloat16 g_wl[(size_t)6*Ee*Ee];
__device__ __nv_bfloat16 g_qh[(size_t)Bb*Nn*Ee],  g_ql[(size_t)Bb*Nn*Ee];
__device__ __nv_bfloat16 g_kh[(size_t)Bb*EXTm*Ee], g_kl[(size_t)Bb*EXTm*Ee];
__device__ __nv_bfloat16 g_vh[(size_t)Bb*EXTm*Ee], g_vl[(size_t)Bb*EXTm*Ee];
__device__ __nv_bfloat16 g_veh[(size_t)Bb*EXTm*Ee], g_vel[(size_t)Bb*EXTm*Ee];

// ---------------- helpers ----------------
__device__ __forceinline__ u32 smem_u32(const void* p){
    u32 a; asm("{ .reg .u64 t; cvta.to.shared.u64 t, %1; cvt.u32.u64 %0, t; }" : "=r"(a) : "l"(p)); return a;
}
__device__ __forceinline__ void cpasync16(u32 dst, const void* src){
    asm volatile("cp.async.ca.shared.global [%0], [%1], 16;" :: "r"(dst), "l"(src) : "memory");
}
__device__ __forceinline__ void ldsm4(u32 r[4], u32 addr){
    asm volatile("ldmatrix.sync.aligned.m8n8.x4.shared.b16 {%0,%1,%2,%3}, [%4];"
                 : "=r"(r[0]), "=r"(r[1]), "=r"(r[2]), "=r"(r[3]) : "r"(addr));
}
__device__ __forceinline__ void ldsm2(u32 r[2], u32 addr){
    asm volatile("ldmatrix.sync.aligned.m8n8.x2.shared.b16 {%0,%1}, [%2];"
                 : "=r"(r[0]), "=r"(r[1]) : "r"(addr));
}
__device__ __forceinline__ void ldsm2t(u32 r[2], u32 addr){
    asm volatile("ldmatrix.sync.aligned.m8n8.x2.trans.shared.b16 {%0,%1}, [%2];"
                 : "=r"(r[0]), "=r"(r[1]) : "r"(addr));
}
__device__ __forceinline__ void mma16816(float c[4], const u32 a[4], u32 b0, u32 b1){
    asm volatile("mma.sync.aligned.m16n8k16.row.col.f32.bf16.bf16.f32 "
                 "{%0,%1,%2,%3}, {%4,%5,%6,%7}, {%8,%9}, {%0,%1,%2,%3};"
                 : "+f"(c[0]), "+f"(c[1]), "+f"(c[2]), "+f"(c[3])
                 : "r"(a[0]), "r"(a[1]), "r"(a[2]), "r"(a[3]), "r"(b0), "r"(b1));
}
__device__ __forceinline__ void st_hilo(__nv_bfloat16* dh, __nv_bfloat16* dl, size_t off, float2 v){
    __nv_bfloat16 h0 = __float2bfloat16(v.x), h1 = __float2bfloat16(v.y);
    __nv_bfloat16 l0 = __float2bfloat16(v.x - __bfloat162float(h0));
    __nv_bfloat16 l1 = __float2bfloat16(v.y - __bfloat162float(h1));
    *(__nv_bfloat162*)&dh[off] = __halves2bfloat162(h0, h1);
    *(__nv_bfloat162*)&dl[off] = __halves2bfloat162(l0, l1);
}

// ---------------- fp32 -> bf16 hi/lo split (GEMM inputs) ----------------
__device__ __forceinline__ void split_store(size_t off, float4 v,
                                            __nv_bfloat16* dh, __nv_bfloat16* dl){
    st_hilo(dh, dl, off,   make_float2(v.x, v.y));
    st_hilo(dh, dl, off+2, make_float2(v.z, v.w));
}

__global__ void __launch_bounds__(256) cvt_w(const float* __restrict__ Wq, const float* __restrict__ Wk,
                                             const float* __restrict__ Wv, const float* __restrict__ Wve,
                                             const float* __restrict__ Woe, const float* __restrict__ Wo)
{
    int w = blockIdx.y;
    const float* W = (w==0)?Wq:(w==1)?Wk:(w==2)?Wv:(w==3)?Wve:(w==4)?Woe:Wo;
    size_t i = ((size_t)blockIdx.x*256 + threadIdx.x)*4;
    float4 v = *(const float4*)(W + i);
    split_store((size_t)w*Ee*Ee + i, v, g_wh, g_wl);
}

__global__ void __launch_bounds__(256) cvt_x(const float* __restrict__ x)
{
    int r = blockIdx.x;
    int b = r >> 8, n = r & 255;
    int e = threadIdx.x * 4;
    float4 v = *(const float4*)(x + ((size_t)n*Bb + b)*Ee + e);
    split_store((size_t)r*Ee + e, v, g_ah, g_al);
}

__global__ void __launch_bounds__(256) cvt_o()
{
    int r = blockIdx.x;
    const float* src = (r < 2048) ? (g_xo + (size_t)r*Ee)
                                  : (g_vec + (size_t)(r-2048)*Ee);
    int e = threadIdx.x * 4;
    float4 v = *(const float4*)(src + e);
    split_store((size_t)r*Ee + e, v, g_ah, g_al);
}

// ========== bf16-split mma.sync GEMM (R5 core) ==========
#define ST_ROW   40
#define MAT_SZ   (128*ST_ROW*2)
#define STAGE_SZ (4*MAT_SZ)
#define MM_SMEM  (2*STAGE_SZ)

__global__ void __launch_bounds__(256) mm_mma(float* __restrict__ Cout, int mode)
{
    extern __shared__ __align__(16) char smraw[];
    const u32 smBase = smem_u32(smraw);
    const int t = threadIdx.x, wid = t >> 5, lid = t & 31;
    const int wm = wid >> 2, wn = wid & 3;
    const int col0 = blockIdx.x * 128;
    const int row0 = blockIdx.y * 128;
    const int unit = (mode == 0) ? (int)blockIdx.z : mode;
    const int arow0 = (unit == 5) ? (2048 + row0) : row0;

    const __nv_bfloat16* srcs[4] = {
        g_ah + (size_t)arow0*Ee,
        g_al + (size_t)arow0*Ee,
        g_wh + (size_t)unit*Ee*Ee + (size_t)col0*Ee,
        g_wl + (size_t)unit*Ee*Ee + (size_t)col0*Ee
    };

    float acc[4][4][4];
#pragma unroll
    for (int i = 0; i < 4; i++)
#pragma unroll
        for (int j = 0; j < 4; j++)
#pragma unroll
            for (int q = 0; q < 4; q++) acc[i][j][q] = 0.f;

    int cp_mat[8], cp_row[8], cp_q[8];
#pragma unroll
    for (int jj = 0; jj < 8; jj++) {
        int id = t + jj*256;
        cp_mat[jj] = id >> 9; int rem = id & 511;
        cp_row[jj] = rem >> 2; cp_q[jj] = rem & 3;
    }

#define ISSUE(kc, stage)                                                          \
    {   int k0 = (kc)*32;                                                         \
        u32 dB = smBase + (stage)*STAGE_SZ;                                       \
        _Pragma("unroll")                                                         \
        for (int jj = 0; jj < 8; jj++) {                                          \
            const __nv_bfloat16* s = srcs[cp_mat[jj]] + (size_t)cp_row[jj]*Ee + k0 + cp_q[jj]*8; \
            cpasync16(dB + cp_mat[jj]*MAT_SZ + cp_row[jj]*(ST_ROW*2) + cp_q[jj]*16, s); \
        }                                                                         \
        asm volatile("cp.async.commit_group;" ::: "memory");                      \
    }

    ISSUE(0, 0);

    const u32 aoff = (u32)(((lid >> 3) & 1) * 8 + (lid & 7));
    const u32 kbl  = (u32)(((lid >> 4) & 1) * 16);

    for (int kc = 0; kc < 32; kc++) {
        int stage = kc & 1;
        if (kc < 31) ISSUE(kc + 1, stage ^ 1);
        if (kc < 31) asm volatile("cp.async.wait_group 1;" ::: "memory");
        else         asm volatile("cp.async.wait_group 0;" ::: "memory");
        __syncthreads();

        u32 base = smBase + stage*STAGE_SZ;
#pragma unroll
        for (int ks = 0; ks < 2; ks++) {
            u32 kb = kbl + ks*32;
            u32 ah[4][4], al[4][4];
            u32 bh0[4], bh1[4], bl0[4], bl1[4];
#pragma unroll
            for (int im = 0; im < 4; im++) {
                u32 row = (u32)(wm*64 + im*16) + aoff;
                ldsm4(ah[im], base + 0*MAT_SZ + row*(ST_ROW*2) + kb);
                ldsm4(al[im], base + 1*MAT_SZ + row*(ST_ROW*2) + kb);
            }
#pragma unroll
            for (int jn = 0; jn < 2; jn++) {
                u32 row = (u32)(wn*32 + jn*16) + aoff;
                u32 rh[4], rl[4];
                ldsm4(rh, base + 2*MAT_SZ + row*(ST_ROW*2) + kb);
                ldsm4(rl, base + 3*MAT_SZ + row*(ST_ROW*2) + kb);
                bh0[jn*2] = rh[0]; bh1[jn*2] = rh[2]; bh0[jn*2+1] = rh[1]; bh1[jn*2+1] = rh[3];
                bl0[jn*2] = rl[0]; bl1[jn*2] = rl[2]; bl0[jn*2+1] = rl[1]; bl1[jn*2+1] = rl[3];
            }
#pragma unroll
            for (int im = 0; im < 4; im++)
#pragma unroll
                for (int n8 = 0; n8 < 4; n8++) {
                    mma16816(acc[im][n8], ah[im], bh0[n8], bh1[n8]);
                    mma16816(acc[im][n8], al[im], bh0[n8], bh1[n8]);
                    mma16816(acc[im][n8], ah[im], bl0[n8], bl1[n8]);
                }
        }
        __syncthreads();
    }

    const int gid = lid >> 2, tig = lid & 3;
#pragma unroll
    for (int im = 0; im < 4; im++) {
#pragma unroll
        for (int n8 = 0; n8 < 4; n8++) {
            int c = col0 + wn*32 + n8*8 + tig*2;
            int r0 = row0 + wm*64 + im*16 + gid;
            int r1 = r0 + 8;
            float2 v0 = make_float2(acc[im][n8][0], acc[im][n8][1]);
            float2 v1 = make_float2(acc[im][n8][2], acc[im][n8][3]);
            if (unit == 0) {
                v0.x *= SCALING; v0.y *= SCALING; v1.x *= SCALING; v1.y *= SCALING;
                st_hilo(g_qh, g_ql, (size_t)r0*Ee + c, v0);
                st_hilo(g_qh, g_ql, (size_t)r1*Ee + c, v1);
            } else if (unit < 4) {
                __nv_bfloat16 *dh, *dl;
                if (unit == 1) { dh = g_kh; dl = g_kl; }
                else if (unit == 2) { dh = g_vh; dl = g_vl; }
                else { dh = g_veh; dl = g_vel; }
                st_hilo(dh, dl, ((size_t)(r0 >> 8)*EXTm + (r0 & 255))*Ee + c, v0);
                st_hilo(dh, dl, ((size_t)(r1 >> 8)*EXTm + (r1 & 255))*Ee + c, v1);
            } else {
                *(float2*)&Cout[(size_t)r0*Ee + c] = v0;
                *(float2*)&Cout[(size_t)r1*Ee + c] = v1;
            }
        }
    }
}

// ---------------- gather (bf16 hi/lo arrays) ----------------
__global__ void __launch_bounds__(256) gather_kernel(const int* __restrict__ idx)
{
    int bm = blockIdx.x;
    int b = bm >> 9, m = bm & 511;
    int s = idx[bm];
    size_t so = ((size_t)b*EXTm + s)      * Ee;
    size_t dd = ((size_t)b*EXTm + Nn + m) * Ee;
    int e = threadIdx.x * 4;
    *(uint2*)&g_kh [dd+e] = *(const uint2*)&g_kh [so+e];
    *(uint2*)&g_kl [dd+e] = *(const uint2*)&g_kl [so+e];
    *(uint2*)&g_vh [dd+e] = *(const uint2*)&g_vh [so+e];
    *(uint2*)&g_vl [dd+e] = *(const uint2*)&g_vl [so+e];
    *(uint2*)&g_veh[dd+e] = *(const uint2*)&g_veh[so+e];
    *(uint2*)&g_vel[dd+e] = *(const uint2*)&g_vel[so+e];
}

// ================= tensor-core attention =================
// block = (nt, h, b); 512 threads (16 warps); 32 query rows; m-tiles of 64.
#define TQ 32
#define SPITCH 776
// smem byte offsets
#define oS  0                 // float S[32][776]            = 99328
#define oQ  99328             // Qh[32][40], Ql  (5120)
#define oK  104448            // Kh[64][40], Kl  (10240)
#define oV  114688            // Vh,Vl,VEh,VEl [64][40] (20480)
#define oW  135168            // Wh[4][32][72], Wl (36864)
#define oPA 172032            // posa float4[768] (12288)
#define oPN 184320            // posn float4[32]  (512)
#define oMF 184832            // maskf float[768] (3072)
#define ATTN_SMEM 187904

__global__ void __launch_bounds__(512, 1) attn_mma(
    const float* __restrict__ pos, const float* __restrict__ epos,
    const float* __restrict__ bias,
    const unsigned char* __restrict__ pmask, const unsigned char* __restrict__ emask)
{
    extern __shared__ __align__(16) char sm[];
    float* S = (float*)(sm + oS);
    float4* posa = (float4*)(sm + oPA);
    float4* posn = (float4*)(sm + oPN);
    float*  maskf = (float*)(sm + oMF);
    const u32 smb = smem_u32(sm);

    const int t = threadIdx.x, w = t >> 5, lid = t & 31;
    const int nt = blockIdx.x, h = blockIdx.y, b = blockIdx.z;
    const int n0 = nt * TQ;

    // ---- init staging ----
    if (t < 256) {                                   // Q hi/lo [32][40]
        int r = t >> 3, q = t & 7;
        u64 gi = ((u64)(b*Nn + n0 + r))*Ee + h*32 + q*4;
        *(uint2*)(sm + oQ + r*80 + q*8)        = *(const uint2*)(g_qh + gi);
        *(uint2*)(sm + oQ + 2560 + r*80 + q*8) = *(const uint2*)(g_ql + gi);
    }
    if (t < 32) {
        const float* pp = pos + ((u64)b*Nn + n0 + t)*3;
        posn[t] = make_float4(pp[0], pp[1], pp[2], pmask[b*Nn + n0 + t] ? 1.f : 0.f);
    }
    for (int i = t; i < EXTm; i += 512) {
        float mq; const float* pp;
        if (i < Nn) { pp = pos  + ((u64)b*Nn + i)*3;      mq = pmask[b*Nn + i] ? 1.f : 0.f; }
        else        { pp = epos + ((u64)b*Mm + i - Nn)*3; mq = emask[b*Mm + i - Nn] ? 1.f : 0.f; }
        posa[i] = make_float4(pp[0], pp[1], pp[2], mq);
        maskf[i] = mq;
    }

    const u32 aoff = (u32)(((lid >> 3) & 1) * 8 + (lid & 7));
    const u32 acol = (u32)(((lid >> 4) & 1) * 16);

    // ---- phase A: S = Q K^T via mma (hi/lo 3-pass) ----
    {
        const int wn = w >> 3, wm8 = w & 7;
        for (int mt = 0; mt < 12; mt++) {
            __syncthreads();
            {   // stage K tile hi/lo [64][40]
                int arr = t >> 8, u = t & 255;
                int row = u >> 2, q = u & 3;
                u64 gi = ((u64)(b*EXTm + mt*64 + row))*Ee + h*32 + q*8;
                const __nv_bfloat16* src = arr ? g_kl : g_kh;
                *(uint4*)(sm + oK + arr*5120 + row*80 + q*16) = *(const uint4*)(src + gi);
            }
            __syncthreads();
            float c[4] = {0.f, 0.f, 0.f, 0.f};
#pragma unroll
            for (int ks = 0; ks < 2; ks++) {
                u32 qa = smb + oQ + (wn*16 + aoff)*80 + acol + ks*32;
                u32 ah[4], al[4];
                ldsm4(ah, qa); ldsm4(al, qa + 2560);
                u32 ka = smb + oK + (wm8*8 + (lid & 7))*80 + ((lid >> 3) & 1)*16 + ks*32;
                u32 bh[2], bl[2];
                ldsm2(bh, ka); ldsm2(bl, ka + 5120);
                mma16816(c, ah, bh[0], bh[1]);
                mma16816(c, al, bh[0], bh[1]);
                mma16816(c, ah, bl[0], bl[1]);
            }
            int row = wn*16 + (lid >> 2);
            int col = mt*64 + wm8*8 + (lid & 3)*2;
            *(float2*)&S[row*SPITCH + col]     = make_float2(c[0], c[1]);
            *(float2*)&S[(row+8)*SPITCH + col] = make_float2(c[2], c[3]);
        }
    }
    __syncthreads();

    // ---- bias + masks (coalesced) ----
    {
        const float* bb = bias + ((u64)(b*Hh + h)*Nn + n0)*EXTm;
#pragma unroll
        for (int rr = 0; rr < 2; rr++) {
            int ni = w*2 + rr;
            float qm = posn[ni].w;
            const float* br = bb + (u64)ni*EXTm;
#pragma unroll
            for (int jj = 0; jj < 6; jj++) {
                int mq = (lid + jj*32)*4;
                float4 sv = *(float4*)&S[ni*SPITCH + mq];
                float4 bv = *(const float4*)(br + mq);
                float4 mv = *(float4*)&maskf[mq];
                sv.x = (qm + mv.x > 0.f) ? NEGINF : sv.x + bv.x;
                sv.y = (qm + mv.y > 0.f) ? NEGINF : sv.y + bv.y;
                sv.z = (qm + mv.z > 0.f) ? NEGINF : sv.z + bv.z;
                sv.w = (qm + mv.w > 0.f) ? NEGINF : sv.w + bv.w;
                *(float4*)&S[ni*SPITCH + mq] = sv;
            }
        }
    }

    // ---- softmax: warp w owns rows w*2, w*2+1 ----
#pragma unroll
    for (int rr = 0; rr < 2; rr++) {
        int ni = w*2 + rr;
        float lm = NEGINF;
#pragma unroll
        for (int i = 0; i < 24; i++) lm = fmaxf(lm, S[ni*SPITCH + lid + i*32]);
#pragma unroll
        for (int o = 16; o; o >>= 1) lm = fmaxf(lm, __shfl_xor_sync(0xffffffffu, lm, o));
        float ls = 0.f;
#pragma unroll
        for (int i = 0; i < 24; i++) {
            float p = __expf(S[ni*SPITCH + lid + i*32] - lm);
            S[ni*SPITCH + lid + i*32] = p;
            ls += p;
        }
#pragma unroll
        for (int o = 16; o; o >>= 1) ls += __shfl_xor_sync(0xffffffffu, ls, o);
        float inv = 1.f / ls;
#pragma unroll
        for (int i = 0; i < 24; i++) S[ni*SPITCH + lid + i*32] *= inv;
    }

    // ---- phase B: 4-channel PV via mma ----
    const int f8 = w & 7;
    const int fn = f8 >> 2, fd = f8 & 3;
    const int ch0 = (w >> 3) * 2;                     // channels ch0, ch0+1
    float acc[2][4];
#pragma unroll
    for (int cc = 0; cc < 2; cc++)
#pragma unroll
        for (int q = 0; q < 4; q++) acc[cc][q] = 0.f;

    for (int mt = 0; mt < 12; mt++) {
        __syncthreads();
        // stage V/VE hi/lo [64][40] (4 arrays)
#pragma unroll
        for (int jj = 0; jj < 2; jj++) {
            int id = t + jj*512;
            int arr = id >> 8, u = id & 255;
            int row = u >> 2, q = u & 3;
            u64 gi = ((u64)(b*EXTm + mt*64 + row))*Ee + h*32 + q*8;
            const __nv_bfloat16* src = (arr==0)?g_vh:(arr==1)?g_vl:(arr==2)?g_veh:g_vel;
            *(uint4*)(sm + oV + arr*5120 + row*80 + q*16) = *(const uint4*)(src + gi);
        }
        // build channel-weight buffers Wch[4][32][72] hi/lo
#pragma unroll
        for (int jj = 0; jj < 4; jj++) {
            int idx = t + jj*512;
            int ml = idx & 63, ni = idx >> 6;
            float4 pm = posa[mt*64 + ml];
            float4 pn = posn[ni];
            float dx = pn.x - pm.x, dy = pn.y - pm.y, dz = pn.z - pm.z;
            float dist = sqrtf(dx*dx + dy*dy + dz*dz);
            if (pn.w + pm.w > 0.f) dist = 1e6f;
            float p = S[ni*SPITCH + mt*64 + ml];
            float f = p / (dist + 1.f);
            if (pn.w > 0.f) f = 0.f;
            float ws[4] = { p, dx*f, dy*f, dz*f };
#pragma unroll
            for (int c = 0; c < 4; c++) {
                __nv_bfloat16 hh = __float2bfloat16(ws[c]);
                __nv_bfloat16 ll = __float2bfloat16(ws[c] - __bfloat162float(hh));
                *(__nv_bfloat16*)(sm + oW + c*4608 + ni*144 + ml*2)          = hh;
                *(__nv_bfloat16*)(sm + oW + 18432 + c*4608 + ni*144 + ml*2)  = ll;
            }
        }
        __syncthreads();
#pragma unroll
        for (int ks = 0; ks < 4; ks++) {
            u32 vrow = (u32)(ks*16 + (lid & 15));
#pragma unroll
            for (int cc = 0; cc < 2; cc++) {
                int c = ch0 + cc;
                u32 varr = (c == 0) ? 2u : 0u;        // 0=Vh,1=Vl,2=VEh,3=VEl
                u32 va = smb + oV + varr*5120 + vrow*80 + fd*16;
                u32 bh[2], bl[2];
                ldsm2t(bh, va);
                ldsm2t(bl, va + 5120);
                u32 wa = smb + oW + c*4608 + (fn*16 + aoff)*144 + acol + ks*32;
                u32 ah[4], al[4];
                ldsm4(ah, wa); ldsm4(al, wa + 18432);
                mma16816(acc[cc], ah, bh[0], bh[1]);
                mma16816(acc[cc], al, bh[0], bh[1]);
                mma16816(acc[cc], ah, bl[0], bl[1]);
            }
        }
    }

    // ---- epilogue: direct stores ----
    {
        int gid = lid >> 2, tig = lid & 3;
        int col = h*32 + fd*8 + tig*2;
#pragma unroll
        for (int cc = 0; cc < 2; cc++) {
            int c = ch0 + cc;
            int r0 = n0 + fn*16 + gid;
            int r1 = r0 + 8;
            float2 v0 = make_float2(acc[cc][0], acc[cc][1]);
            float2 v1 = make_float2(acc[cc][2], acc[cc][3]);
            if (c == 0) {
                *(float2*)&g_xo[((u64)(b*Nn + r0))*Ee + col] = v0;
                *(float2*)&g_xo[((u64)(b*Nn + r1))*Ee + col] = v1;
            } else {
                *(float2*)&g_vec[(((u64)(b*Nn + r0))*3 + (c-1))*Ee + col] = v0;
                *(float2*)&g_vec[(((u64)(b*Nn + r1))*3 + (c-1))*Ee + col] = v1;
            }
        }
    }
}

// ---------------- host entry ----------------
extern "C" void kernel_launch(void* const* d_in, const int* in_sizes, int n_in,
                              void* d_out, int out_size)
{
    const float* x    = (const float*)d_in[0];
    const float* pos  = (const float*)d_in[1];
    const float* epos = (const float*)d_in[2];
    const float* bias = (const float*)d_in[3];
    const unsigned char* pmask = (const unsigned char*)d_in[4];
    const unsigned char* emask = (const unsigned char*)d_in[5];
    const int*   idx  = (const int*)d_in[6];
    const float* Wq   = (const float*)d_in[7];
    const float* Wk   = (const float*)d_in[8];
    const float* Wv   = (const float*)d_in[9];
    const float* Wve  = (const float*)d_in[10];
    const float* Wo   = (const float*)d_in[11];
    const float* Woe  = (const float*)d_in[12];
    float* out = (float*)d_out;

    cudaFuncSetAttribute(mm_mma, cudaFuncAttributeMaxDynamicSharedMemorySize, MM_SMEM);
    cudaFuncSetAttribute(attn_mma, cudaFuncAttributeMaxDynamicSharedMemorySize, ATTN_SMEM);

    cvt_w<<<dim3(1024, 6), 256>>>(Wq, Wk, Wv, Wve, Woe, Wo);
    cvt_x<<<2048, 256>>>(x);

    mm_mma<<<dim3(8, 16, 4), 256, MM_SMEM>>>(nullptr, 0);    // q,k,v,ve projections

    gather_kernel<<<Bb*Mm, 256>>>(idx);

    attn_mma<<<dim3(8, 32, 8), 512, ATTN_SMEM>>>(pos, epos, bias, pmask, emask);

    cvt_o<<<8192, 256>>>();

    mm_mma<<<dim3(8, 16, 1), 256, MM_SMEM>>>(out, 4);                       // xo @ Woe^T
    mm_mma<<<dim3(8, 48, 1), 256, MM_SMEM>>>(out + (size_t)2048*Ee, 5);     // vec @ Wo^T
}

// round 8
// speedup vs baseline: 2.9694x; 1.0316x over previous
#include <cuda_runtime.h>
#include <cuda_bf16.h>
#include <cstdint>
#include <cstddef>

typedef unsigned int u32;
typedef unsigned long long u64;

#define Bb   8
#define Nn   256
#define Mm   512
#define EXTm 768
#define Ee   1024
#define Hh   32
#define SCALING 0.17677669529663687f
#define NEGINF  -3.402823466e38f

// ---------------- scratch ----------------
__device__ float g_xo[(size_t)Bb*Nn*Ee];
__device__ float g_vec[(size_t)Bb*Nn*3*Ee];
__device__ float4 g_pd[(size_t)Bb*Nn*EXTm];
__device__ __nv_bfloat16 g_ah[(size_t)8192*Ee];
__device__ __nv_bfloat16 g_al[(size_t)8192*Ee];
__device__ __nv_bfloat16 g_wh[(size_t)6*Ee*Ee];
__device__ __nv_bfloat16 g_wl[(size_t)6*Ee*Ee];
__device__ __nv_bfloat16 g_qh[(size_t)Bb*Nn*Ee],  g_ql[(size_t)Bb*Nn*Ee];
__device__ __nv_bfloat16 g_kh[(size_t)Bb*EXTm*Ee], g_kl[(size_t)Bb*EXTm*Ee];
__device__ __nv_bfloat16 g_vh[(size_t)Bb*EXTm*Ee], g_vl[(size_t)Bb*EXTm*Ee];
__device__ __nv_bfloat16 g_veh[(size_t)Bb*EXTm*Ee], g_vel[(size_t)Bb*EXTm*Ee];

// ---------------- helpers ----------------
__device__ __forceinline__ u32 smem_u32(const void* p){
    u32 a; asm("{ .reg .u64 t; cvta.to.shared.u64 t, %1; cvt.u32.u64 %0, t; }" : "=r"(a) : "l"(p)); return a;
}
__device__ __forceinline__ void cpasync16(u32 dst, const void* src){
    asm volatile("cp.async.ca.shared.global [%0], [%1], 16;" :: "r"(dst), "l"(src) : "memory");
}
__device__ __forceinline__ void ldsm4(u32 r[4], u32 addr){
    asm volatile("ldmatrix.sync.aligned.m8n8.x4.shared.b16 {%0,%1,%2,%3}, [%4];"
                 : "=r"(r[0]), "=r"(r[1]), "=r"(r[2]), "=r"(r[3]) : "r"(addr));
}
__device__ __forceinline__ void ldsm2(u32 r[2], u32 addr){
    asm volatile("ldmatrix.sync.aligned.m8n8.x2.shared.b16 {%0,%1}, [%2];"
                 : "=r"(r[0]), "=r"(r[1]) : "r"(addr));
}
__device__ __forceinline__ void ldsm2t(u32 r[2], u32 addr){
    asm volatile("ldmatrix.sync.aligned.m8n8.x2.trans.shared.b16 {%0,%1}, [%2];"
                 : "=r"(r[0]), "=r"(r[1]) : "r"(addr));
}
__device__ __forceinline__ void mma16816(float c[4], const u32 a[4], u32 b0, u32 b1){
    asm volatile("mma.sync.aligned.m16n8k16.row.col.f32.bf16.bf16.f32 "
                 "{%0,%1,%2,%3}, {%4,%5,%6,%7}, {%8,%9}, {%0,%1,%2,%3};"
                 : "+f"(c[0]), "+f"(c[1]), "+f"(c[2]), "+f"(c[3])
                 : "r"(a[0]), "r"(a[1]), "r"(a[2]), "r"(a[3]), "r"(b0), "r"(b1));
}
__device__ __forceinline__ void st_hilo(__nv_bfloat16* dh, __nv_bfloat16* dl, size_t off, float2 v){
    __nv_bfloat16 h0 = __float2bfloat16(v.x), h1 = __float2bfloat16(v.y);
    __nv_bfloat16 l0 = __float2bfloat16(v.x - __bfloat162float(h0));
    __nv_bfloat16 l1 = __float2bfloat16(v.y - __bfloat162float(h1));
    *(__nv_bfloat162*)&dh[off] = __halves2bfloat162(h0, h1);
    *(__nv_bfloat162*)&dl[off] = __halves2bfloat162(l0, l1);
}

// ---------------- fp32 -> bf16 hi/lo split (GEMM inputs) ----------------
__device__ __forceinline__ void split_store(size_t off, float4 v,
                                            __nv_bfloat16* dh, __nv_bfloat16* dl){
    st_hilo(dh, dl, off,   make_float2(v.x, v.y));
    st_hilo(dh, dl, off+2, make_float2(v.z, v.w));
}

__global__ void __launch_bounds__(256) cvt_w(const float* __restrict__ Wq, const float* __restrict__ Wk,
                                             const float* __restrict__ Wv, const float* __restrict__ Wve,
                                             const float* __restrict__ Woe, const float* __restrict__ Wo)
{
    int w = blockIdx.y;
    const float* W = (w==0)?Wq:(w==1)?Wk:(w==2)?Wv:(w==3)?Wve:(w==4)?Woe:Wo;
    size_t i = ((size_t)blockIdx.x*256 + threadIdx.x)*4;
    float4 v = *(const float4*)(W + i);
    split_store((size_t)w*Ee*Ee + i, v, g_wh, g_wl);
}

__global__ void __launch_bounds__(256) cvt_x(const float* __restrict__ x)
{
    int r = blockIdx.x;
    int b = r >> 8, n = r & 255;
    int e = threadIdx.x * 4;
    float4 v = *(const float4*)(x + ((size_t)n*Bb + b)*Ee + e);
    split_store((size_t)r*Ee + e, v, g_ah, g_al);
}

__global__ void __launch_bounds__(256) cvt_o()
{
    int r = blockIdx.x;
    const float* src = (r < 2048) ? (g_xo + (size_t)r*Ee)
                                  : (g_vec + (size_t)(r-2048)*Ee);
    int e = threadIdx.x * 4;
    float4 v = *(const float4*)(src + e);
    split_store((size_t)r*Ee + e, v, g_ah, g_al);
}

// ---------------- geometry precompute: pd = delta/(dist+1), masks folded ----------------
__global__ void __launch_bounds__(256) geom_kernel(
    const float* __restrict__ pos, const float* __restrict__ epos,
    const unsigned char* __restrict__ pmask, const unsigned char* __restrict__ emask)
{
    int bn = blockIdx.x;                  // b*256 + n
    int b = bn >> 8, n = bn & 255;
    const float* pq = pos + (size_t)(b*Nn + n)*3;
    float px = pq[0], py = pq[1], pz = pq[2];
    unsigned int qm = pmask[b*Nn + n];
    for (int m = threadIdx.x; m < EXTm; m += 256) {
        float ax, ay, az; unsigned int km;
        if (m < Nn) {
            const float* pp = pos + (size_t)(b*Nn + m)*3;
            ax = pp[0]; ay = pp[1]; az = pp[2];
            km = pmask[b*Nn + m];
        } else {
            const float* pp = epos + (size_t)(b*Mm + m - Nn)*3;
            ax = pp[0]; ay = pp[1]; az = pp[2];
            km = emask[b*Mm + m - Nn];
        }
        float dx = px - ax, dy = py - ay, dz = pz - az;
        float dist = sqrtf(dx*dx + dy*dy + dz*dz);
        if (qm | km) dist = 1e6f;
        float f = 1.f / (dist + 1.f);
        if (qm) f = 0.f;
        g_pd[(size_t)bn*EXTm + m] = make_float4(dx*f, dy*f, dz*f, 0.f);
    }
}

// ========== bf16-split mma.sync GEMM (R5 core) ==========
#define ST_ROW   40
#define MAT_SZ   (128*ST_ROW*2)
#define STAGE_SZ (4*MAT_SZ)
#define MM_SMEM  (2*STAGE_SZ)

__global__ void __launch_bounds__(256) mm_mma(float* __restrict__ Cout, int mode)
{
    extern __shared__ __align__(16) char smraw[];
    const u32 smBase = smem_u32(smraw);
    const int t = threadIdx.x, wid = t >> 5, lid = t & 31;
    const int wm = wid >> 2, wn = wid & 3;
    const int col0 = blockIdx.x * 128;
    const int row0 = blockIdx.y * 128;
    const int unit = (mode == 0) ? (int)blockIdx.z : mode;
    const int arow0 = (unit == 5) ? (2048 + row0) : row0;

    const __nv_bfloat16* srcs[4] = {
        g_ah + (size_t)arow0*Ee,
        g_al + (size_t)arow0*Ee,
        g_wh + (size_t)unit*Ee*Ee + (size_t)col0*Ee,
        g_wl + (size_t)unit*Ee*Ee + (size_t)col0*Ee
    };

    float acc[4][4][4];
#pragma unroll
    for (int i = 0; i < 4; i++)
#pragma unroll
        for (int j = 0; j < 4; j++)
#pragma unroll
            for (int q = 0; q < 4; q++) acc[i][j][q] = 0.f;

    int cp_mat[8], cp_row[8], cp_q[8];
#pragma unroll
    for (int jj = 0; jj < 8; jj++) {
        int id = t + jj*256;
        cp_mat[jj] = id >> 9; int rem = id & 511;
        cp_row[jj] = rem >> 2; cp_q[jj] = rem & 3;
    }

#define ISSUE(kc, stage)                                                          \
    {   int k0 = (kc)*32;                                                         \
        u32 dB = smBase + (stage)*STAGE_SZ;                                       \
        _Pragma("unroll")                                                         \
        for (int jj = 0; jj < 8; jj++) {                                          \
            const __nv_bfloat16* s = srcs[cp_mat[jj]] + (size_t)cp_row[jj]*Ee + k0 + cp_q[jj]*8; \
            cpasync16(dB + cp_mat[jj]*MAT_SZ + cp_row[jj]*(ST_ROW*2) + cp_q[jj]*16, s); \
        }                                                                         \
        asm volatile("cp.async.commit_group;" ::: "memory");                      \
    }

    ISSUE(0, 0);

    const u32 aoff = (u32)(((lid >> 3) & 1) * 8 + (lid & 7));
    const u32 kbl  = (u32)(((lid >> 4) & 1) * 16);

    for (int kc = 0; kc < 32; kc++) {
        int stage = kc & 1;
        if (kc < 31) ISSUE(kc + 1, stage ^ 1);
        if (kc < 31) asm volatile("cp.async.wait_group 1;" ::: "memory");
        else         asm volatile("cp.async.wait_group 0;" ::: "memory");
        __syncthreads();

        u32 base = smBase + stage*STAGE_SZ;
#pragma unroll
        for (int ks = 0; ks < 2; ks++) {
            u32 kb = kbl + ks*32;
            u32 ah[4][4], al[4][4];
            u32 bh0[4], bh1[4], bl0[4], bl1[4];
#pragma unroll
            for (int im = 0; im < 4; im++) {
                u32 row = (u32)(wm*64 + im*16) + aoff;
                ldsm4(ah[im], base + 0*MAT_SZ + row*(ST_ROW*2) + kb);
                ldsm4(al[im], base + 1*MAT_SZ + row*(ST_ROW*2) + kb);
            }
#pragma unroll
            for (int jn = 0; jn < 2; jn++) {
                u32 row = (u32)(wn*32 + jn*16) + aoff;
                u32 rh[4], rl[4];
                ldsm4(rh, base + 2*MAT_SZ + row*(ST_ROW*2) + kb);
                ldsm4(rl, base + 3*MAT_SZ + row*(ST_ROW*2) + kb);
                bh0[jn*2] = rh[0]; bh1[jn*2] = rh[2]; bh0[jn*2+1] = rh[1]; bh1[jn*2+1] = rh[3];
                bl0[jn*2] = rl[0]; bl1[jn*2] = rl[2]; bl0[jn*2+1] = rl[1]; bl1[jn*2+1] = rl[3];
            }
#pragma unroll
            for (int im = 0; im < 4; im++)
#pragma unroll
                for (int n8 = 0; n8 < 4; n8++) {
                    mma16816(acc[im][n8], ah[im], bh0[n8], bh1[n8]);
                    mma16816(acc[im][n8], al[im], bh0[n8], bh1[n8]);
                    mma16816(acc[im][n8], ah[im], bl0[n8], bl1[n8]);
                }
        }
        __syncthreads();
    }

    const int gid = lid >> 2, tig = lid & 3;
#pragma unroll
    for (int im = 0; im < 4; im++) {
#pragma unroll
        for (int n8 = 0; n8 < 4; n8++) {
            int c = col0 + wn*32 + n8*8 + tig*2;
            int r0 = row0 + wm*64 + im*16 + gid;
            int r1 = r0 + 8;
            float2 v0 = make_float2(acc[im][n8][0], acc[im][n8][1]);
            float2 v1 = make_float2(acc[im][n8][2], acc[im][n8][3]);
            if (unit == 0) {
                v0.x *= SCALING; v0.y *= SCALING; v1.x *= SCALING; v1.y *= SCALING;
                st_hilo(g_qh, g_ql, (size_t)r0*Ee + c, v0);
                st_hilo(g_qh, g_ql, (size_t)r1*Ee + c, v1);
            } else if (unit < 4) {
                __nv_bfloat16 *dh, *dl;
                if (unit == 1) { dh = g_kh; dl = g_kl; }
                else if (unit == 2) { dh = g_vh; dl = g_vl; }
                else { dh = g_veh; dl = g_vel; }
                st_hilo(dh, dl, ((size_t)(r0 >> 8)*EXTm + (r0 & 255))*Ee + c, v0);
                st_hilo(dh, dl, ((size_t)(r1 >> 8)*EXTm + (r1 & 255))*Ee + c, v1);
            } else {
                *(float2*)&Cout[(size_t)r0*Ee + c] = v0;
                *(float2*)&Cout[(size_t)r1*Ee + c] = v1;
            }
        }
    }
}

// ---------------- gather (bf16 hi/lo arrays) ----------------
__global__ void __launch_bounds__(256) gather_kernel(const int* __restrict__ idx)
{
    int bm = blockIdx.x;
    int b = bm >> 9, m = bm & 511;
    int s = idx[bm];
    size_t so = ((size_t)b*EXTm + s)      * Ee;
    size_t dd = ((size_t)b*EXTm + Nn + m) * Ee;
    int e = threadIdx.x * 4;
    *(uint2*)&g_kh [dd+e] = *(const uint2*)&g_kh [so+e];
    *(uint2*)&g_kl [dd+e] = *(const uint2*)&g_kl [so+e];
    *(uint2*)&g_vh [dd+e] = *(const uint2*)&g_vh [so+e];
    *(uint2*)&g_vl [dd+e] = *(const uint2*)&g_vl [so+e];
    *(uint2*)&g_veh[dd+e] = *(const uint2*)&g_veh[so+e];
    *(uint2*)&g_vel[dd+e] = *(const uint2*)&g_vel[so+e];
}

// ================= tensor-core attention =================
#define TQ 32
#define SPITCH 776
#define oS  0                 // float S[32][776]            = 99328
#define oQ  99328             // Qh[32][40], Ql  (5120)
#define oK  104448            // Kh[64][40], Kl  (10240)
#define oV  114688            // Vh,Vl,VEh,VEl [64][40] (20480)
#define oW  135168            // Wh[4][32][72], Wl (36864) -> ends 172032
#define oPN 172032            // posn-mask float[32] (128)
#define oMF 172160            // maskf float[768] (3072)
#define ATTN_SMEM 175232

__global__ void __launch_bounds__(512, 1) attn_mma(
    const float* __restrict__ pos, const float* __restrict__ epos,
    const float* __restrict__ bias,
    const unsigned char* __restrict__ pmask, const unsigned char* __restrict__ emask)
{
    extern __shared__ __align__(16) char sm[];
    float* S = (float*)(sm + oS);
    float*  qmn  = (float*)(sm + oPN);
    float*  maskf = (float*)(sm + oMF);
    const u32 smb = smem_u32(sm);

    const int t = threadIdx.x, w = t >> 5, lid = t & 31;
    const int nt = blockIdx.x, h = blockIdx.y, b = blockIdx.z;
    const int n0 = nt * TQ;

    // ---- init staging ----
    if (t < 256) {                                   // Q hi/lo [32][40]
        int r = t >> 3, q = t & 7;
        u64 gi = ((u64)(b*Nn + n0 + r))*Ee + h*32 + q*4;
        *(uint2*)(sm + oQ + r*80 + q*8)        = *(const uint2*)(g_qh + gi);
        *(uint2*)(sm + oQ + 2560 + r*80 + q*8) = *(const uint2*)(g_ql + gi);
    }
    if (t < 32) qmn[t] = pmask[b*Nn + n0 + t] ? 1.f : 0.f;
    for (int i = t; i < EXTm; i += 512) {
        unsigned int mq = (i < Nn) ? pmask[b*Nn + i] : emask[b*Mm + i - Nn];
        maskf[i] = mq ? 1.f : 0.f;
    }

    const u32 aoff = (u32)(((lid >> 3) & 1) * 8 + (lid & 7));
    const u32 acol = (u32)(((lid >> 4) & 1) * 16);

    // ---- phase A: S = Q K^T via mma (hi/lo 3-pass) ----
    {
        const int wn = w >> 3, wm8 = w & 7;
        for (int mt = 0; mt < 12; mt++) {
            __syncthreads();
            {   // stage K tile hi/lo [64][40]
                int arr = t >> 8, u = t & 255;
                int row = u >> 2, q = u & 3;
                u64 gi = ((u64)(b*EXTm + mt*64 + row))*Ee + h*32 + q*8;
                const __nv_bfloat16* src = arr ? g_kl : g_kh;
                *(uint4*)(sm + oK + arr*5120 + row*80 + q*16) = *(const uint4*)(src + gi);
            }
            __syncthreads();
            float c[4] = {0.f, 0.f, 0.f, 0.f};
#pragma unroll
            for (int ks = 0; ks < 2; ks++) {
                u32 qa = smb + oQ + (wn*16 + aoff)*80 + acol + ks*32;
                u32 ah[4], al[4];
                ldsm4(ah, qa); ldsm4(al, qa + 2560);
                u32 ka = smb + oK + (wm8*8 + (lid & 7))*80 + ((lid >> 3) & 1)*16 + ks*32;
                u32 bh[2], bl[2];
                ldsm2(bh, ka); ldsm2(bl, ka + 5120);
                mma16816(c, ah, bh[0], bh[1]);
                mma16816(c, al, bh[0], bh[1]);
                mma16816(c, ah, bl[0], bl[1]);
            }
            int row = wn*16 + (lid >> 2);
            int col = mt*64 + wm8*8 + (lid & 3)*2;
            *(float2*)&S[row*SPITCH + col]     = make_float2(c[0], c[1]);
            *(float2*)&S[(row+8)*SPITCH + col] = make_float2(c[2], c[3]);
        }
    }
    __syncthreads();

    // ---- bias + masks (coalesced) ----
    {
        const float* bb = bias + ((u64)(b*Hh + h)*Nn + n0)*EXTm;
#pragma unroll
        for (int rr = 0; rr < 2; rr++) {
            int ni = w*2 + rr;
            float qm = qmn[ni];
            const float* br = bb + (u64)ni*EXTm;
#pragma unroll
            for (int jj = 0; jj < 6; jj++) {
                int mq = (lid + jj*32)*4;
                float4 sv = *(float4*)&S[ni*SPITCH + mq];
                float4 bv = *(const float4*)(br + mq);
                float4 mv = *(float4*)&maskf[mq];
                sv.x = (qm + mv.x > 0.f) ? NEGINF : sv.x + bv.x;
                sv.y = (qm + mv.y > 0.f) ? NEGINF : sv.y + bv.y;
                sv.z = (qm + mv.z > 0.f) ? NEGINF : sv.z + bv.z;
                sv.w = (qm + mv.w > 0.f) ? NEGINF : sv.w + bv.w;
                *(float4*)&S[ni*SPITCH + mq] = sv;
            }
        }
    }

    // ---- softmax ----
#pragma unroll
    for (int rr = 0; rr < 2; rr++) {
        int ni = w*2 + rr;
        float lm = NEGINF;
#pragma unroll
        for (int i = 0; i < 24; i++) lm = fmaxf(lm, S[ni*SPITCH + lid + i*32]);
#pragma unroll
        for (int o = 16; o; o >>= 1) lm = fmaxf(lm, __shfl_xor_sync(0xffffffffu, lm, o));
        float ls = 0.f;
#pragma unroll
        for (int i = 0; i < 24; i++) {
            float p = __expf(S[ni*SPITCH + lid + i*32] - lm);
            S[ni*SPITCH + lid + i*32] = p;
            ls += p;
        }
#pragma unroll
        for (int o = 16; o; o >>= 1) ls += __shfl_xor_sync(0xffffffffu, ls, o);
        float inv = 1.f / ls;
#pragma unroll
        for (int i = 0; i < 24; i++) S[ni*SPITCH + lid + i*32] *= inv;
    }

    // ---- phase B: 4-channel PV via mma, weights from precomputed geometry ----
    const int f8 = w & 7;
    const int fn = f8 >> 2, fd = f8 & 3;
    const int ch0 = (w >> 3) * 2;
    float acc[2][4];
#pragma unroll
    for (int cc = 0; cc < 2; cc++)
#pragma unroll
        for (int q = 0; q < 4; q++) acc[cc][q] = 0.f;

    const float4* pdb = g_pd + (u64)(b*Nn + n0)*EXTm;

    for (int mt = 0; mt < 12; mt++) {
        __syncthreads();
        // stage V/VE hi/lo [64][40]
#pragma unroll
        for (int jj = 0; jj < 2; jj++) {
            int id = t + jj*512;
            int arr = id >> 8, u = id & 255;
            int row = u >> 2, q = u & 3;
            u64 gi = ((u64)(b*EXTm + mt*64 + row))*Ee + h*32 + q*8;
            const __nv_bfloat16* src = (arr==0)?g_vh:(arr==1)?g_vl:(arr==2)?g_veh:g_vel;
            *(uint4*)(sm + oV + arr*5120 + row*80 + q*16) = *(const uint4*)(src + gi);
        }
        // weight build: 1024 m-pairs; w_c = p * pd_c; bf16x2 packed stores
#pragma unroll
        for (int jj = 0; jj < 2; jj++) {
            int idx = t + jj*512;                  // 0..1023
            int ni = idx >> 5, pr = idx & 31, ml = pr*2;
            int m = mt*64 + ml;
            float2 pp = *(float2*)&S[ni*SPITCH + m];
            float4 d0 = pdb[(u64)ni*EXTm + m];
            float4 d1 = pdb[(u64)ni*EXTm + m + 1];
            float wsa[4] = { pp.x, pp.x*d0.x, pp.x*d0.y, pp.x*d0.z };
            float wsb[4] = { pp.y, pp.y*d1.x, pp.y*d1.y, pp.y*d1.z };
#pragma unroll
            for (int c = 0; c < 4; c++) {
                __nv_bfloat16 ha = __float2bfloat16(wsa[c]);
                __nv_bfloat16 hb = __float2bfloat16(wsb[c]);
                __nv_bfloat16 la = __float2bfloat16(wsa[c] - __bfloat162float(ha));
                __nv_bfloat16 lb = __float2bfloat16(wsb[c] - __bfloat162float(hb));
                *(__nv_bfloat162*)(sm + oW + c*4608 + ni*144 + ml*2)         = __halves2bfloat162(ha, hb);
                *(__nv_bfloat162*)(sm + oW + 18432 + c*4608 + ni*144 + ml*2) = __halves2bfloat162(la, lb);
            }
        }
        __syncthreads();
#pragma unroll
        for (int ks = 0; ks < 4; ks++) {
            u32 vrow = (u32)(ks*16 + (lid & 15));
#pragma unroll
            for (int cc = 0; cc < 2; cc++) {
                int c = ch0 + cc;
                u32 varr = (c == 0) ? 2u : 0u;
                u32 va = smb + oV + varr*5120 + vrow*80 + fd*16;
                u32 bh[2], bl[2];
                ldsm2t(bh, va);
                ldsm2t(bl, va + 5120);
                u32 wa = smb + oW + c*4608 + (fn*16 + aoff)*144 + acol + ks*32;
                u32 ah[4], al[4];
                ldsm4(ah, wa); ldsm4(al, wa + 18432);
                mma16816(acc[cc], ah, bh[0], bh[1]);
                mma16816(acc[cc], al, bh[0], bh[1]);
                mma16816(acc[cc], ah, bl[0], bl[1]);
            }
        }
    }

    // ---- epilogue ----
    {
        int gid = lid >> 2, tig = lid & 3;
        int col = h*32 + fd*8 + tig*2;
#pragma unroll
        for (int cc = 0; cc < 2; cc++) {
            int c = ch0 + cc;
            int r0 = n0 + fn*16 + gid;
            int r1 = r0 + 8;
            float2 v0 = make_float2(acc[cc][0], acc[cc][1]);
            float2 v1 = make_float2(acc[cc][2], acc[cc][3]);
            if (c == 0) {
                *(float2*)&g_xo[((u64)(b*Nn + r0))*Ee + col] = v0;
                *(float2*)&g_xo[((u64)(b*Nn + r1))*Ee + col] = v1;
            } else {
                *(float2*)&g_vec[(((u64)(b*Nn + r0))*3 + (c-1))*Ee + col] = v0;
                *(float2*)&g_vec[(((u64)(b*Nn + r1))*3 + (c-1))*Ee + col] = v1;
            }
        }
    }
}

// ---------------- host entry ----------------
extern "C" void kernel_launch(void* const* d_in, const int* in_sizes, int n_in,
                              void* d_out, int out_size)
{
    const float* x    = (const float*)d_in[0];
    const float* pos  = (const float*)d_in[1];
    const float* epos = (const float*)d_in[2];
    const float* bias = (const float*)d_in[3];
    const unsigned char* pmask = (const unsigned char*)d_in[4];
    const unsigned char* emask = (const unsigned char*)d_in[5];
    const int*   idx  = (const int*)d_in[6];
    const float* Wq   = (const float*)d_in[7];
    const float* Wk   = (const float*)d_in[8];
    const float* Wv   = (const float*)d_in[9];
    const float* Wve  = (const float*)d_in[10];
    const float* Wo   = (const float*)d_in[11];
    const float* Woe  = (const float*)d_in[12];
    float* out = (float*)d_out;

    cudaFuncSetAttribute(mm_mma, cudaFuncAttributeMaxDynamicSharedMemorySize, MM_SMEM);
    cudaFuncSetAttribute(attn_mma, cudaFuncAttributeMaxDynamicSharedMemorySize, ATTN_SMEM);

    geom_kernel<<<Bb*Nn, 256>>>(pos, epos, pmask, emask);
    cvt_w<<<dim3(1024, 6), 256>>>(Wq, Wk, Wv, Wve, Woe, Wo);
    cvt_x<<<2048, 256>>>(x);

    mm_mma<<<dim3(8, 16, 4), 256, MM_SMEM>>>(nullptr, 0);    // q,k,v,ve projections

    gather_kernel<<<Bb*Mm, 256>>>(idx);

    attn_mma<<<dim3(8, 32, 8), 512, ATTN_SMEM>>>(pos, epos, bias, pmask, emask);

    cvt_o<<<8192, 256>>>();

    mm_mma<<<dim3(8, 16, 1), 256, MM_SMEM>>>(out, 4);                       // xo @ Woe^T
    mm_mma<<<dim3(8, 48, 1), 256, MM_SMEM>>>(out + (size_t)2048*Ee, 5);     // vec @ Wo^T
}

// round 9
// speedup vs baseline: 3.2337x; 1.0890x over previous
#include <cuda_runtime.h>
#include <cuda_bf16.h>
#include <cstdint>
#include <cstddef>

typedef unsigned int u32;
typedef unsigned long long u64;

#define Bb   8
#define Nn   256
#define Mm   512
#define EXTm 768
#define Ee   1024
#define Hh   32
#define SCALING 0.17677669529663687f
#define NEGINF  -3.402823466e38f

// ---------------- scratch ----------------
__device__ float4 g_pd[(size_t)Bb*Nn*EXTm];
__device__ __nv_bfloat16 g_ah[(size_t)8192*Ee];
__device__ __nv_bfloat16 g_al[(size_t)8192*Ee];
__device__ __nv_bfloat16 g_wh[(size_t)6*Ee*Ee];
__device__ __nv_bfloat16 g_wl[(size_t)6*Ee*Ee];
__device__ __nv_bfloat16 g_qh[(size_t)Bb*Nn*Ee],  g_ql[(size_t)Bb*Nn*Ee];
__device__ __nv_bfloat16 g_kh[(size_t)Bb*EXTm*Ee], g_kl[(size_t)Bb*EXTm*Ee];
__device__ __nv_bfloat16 g_vh[(size_t)Bb*EXTm*Ee], g_vl[(size_t)Bb*EXTm*Ee];
__device__ __nv_bfloat16 g_veh[(size_t)Bb*EXTm*Ee], g_vel[(size_t)Bb*EXTm*Ee];

// ---------------- helpers ----------------
__device__ __forceinline__ u32 smem_u32(const void* p){
    u32 a; asm("{ .reg .u64 t; cvta.to.shared.u64 t, %1; cvt.u32.u64 %0, t; }" : "=r"(a) : "l"(p)); return a;
}
__device__ __forceinline__ void cpasync16(u32 dst, const void* src){
    asm volatile("cp.async.ca.shared.global [%0], [%1], 16;" :: "r"(dst), "l"(src) : "memory");
}
__device__ __forceinline__ void ldsm4(u32 r[4], u32 addr){
    asm volatile("ldmatrix.sync.aligned.m8n8.x4.shared.b16 {%0,%1,%2,%3}, [%4];"
                 : "=r"(r[0]), "=r"(r[1]), "=r"(r[2]), "=r"(r[3]) : "r"(addr));
}
__device__ __forceinline__ void ldsm2(u32 r[2], u32 addr){
    asm volatile("ldmatrix.sync.aligned.m8n8.x2.shared.b16 {%0,%1}, [%2];"
                 : "=r"(r[0]), "=r"(r[1]) : "r"(addr));
}
__device__ __forceinline__ void ldsm2t(u32 r[2], u32 addr){
    asm volatile("ldmatrix.sync.aligned.m8n8.x2.trans.shared.b16 {%0,%1}, [%2];"
                 : "=r"(r[0]), "=r"(r[1]) : "r"(addr));
}
__device__ __forceinline__ void mma16816(float c[4], const u32 a[4], u32 b0, u32 b1){
    asm volatile("mma.sync.aligned.m16n8k16.row.col.f32.bf16.bf16.f32 "
                 "{%0,%1,%2,%3}, {%4,%5,%6,%7}, {%8,%9}, {%0,%1,%2,%3};"
                 : "+f"(c[0]), "+f"(c[1]), "+f"(c[2]), "+f"(c[3])
                 : "r"(a[0]), "r"(a[1]), "r"(a[2]), "r"(a[3]), "r"(b0), "r"(b1));
}
__device__ __forceinline__ void st_hilo(__nv_bfloat16* dh, __nv_bfloat16* dl, size_t off, float2 v){
    __nv_bfloat16 h0 = __float2bfloat16(v.x), h1 = __float2bfloat16(v.y);
    __nv_bfloat16 l0 = __float2bfloat16(v.x - __bfloat162float(h0));
    __nv_bfloat16 l1 = __float2bfloat16(v.y - __bfloat162float(h1));
    *(__nv_bfloat162*)&dh[off] = __halves2bfloat162(h0, h1);
    *(__nv_bfloat162*)&dl[off] = __halves2bfloat162(l0, l1);
}

__device__ __forceinline__ void split_store(size_t off, float4 v,
                                            __nv_bfloat16* dh, __nv_bfloat16* dl){
    st_hilo(dh, dl, off,   make_float2(v.x, v.y));
    st_hilo(dh, dl, off+2, make_float2(v.z, v.w));
}

__global__ void __launch_bounds__(256) cvt_w(const float* __restrict__ Wq, const float* __restrict__ Wk,
                                             const float* __restrict__ Wv, const float* __restrict__ Wve,
                                             const float* __restrict__ Woe, const float* __restrict__ Wo)
{
    int w = blockIdx.y;
    const float* W = (w==0)?Wq:(w==1)?Wk:(w==2)?Wv:(w==3)?Wve:(w==4)?Woe:Wo;
    size_t i = ((size_t)blockIdx.x*256 + threadIdx.x)*4;
    float4 v = *(const float4*)(W + i);
    split_store((size_t)w*Ee*Ee + i, v, g_wh, g_wl);
}

__global__ void __launch_bounds__(256) cvt_x(const float* __restrict__ x)
{
    int r = blockIdx.x;
    int b = r >> 8, n = r & 255;
    int e = threadIdx.x * 4;
    float4 v = *(const float4*)(x + ((size_t)n*Bb + b)*Ee + e);
    split_store((size_t)r*Ee + e, v, g_ah, g_al);
}

// ---------------- geometry precompute ----------------
__global__ void __launch_bounds__(256) geom_kernel(
    const float* __restrict__ pos, const float* __restrict__ epos,
    const unsigned char* __restrict__ pmask, const unsigned char* __restrict__ emask)
{
    int bn = blockIdx.x;
    int b = bn >> 8, n = bn & 255;
    const float* pq = pos + (size_t)(b*Nn + n)*3;
    float px = pq[0], py = pq[1], pz = pq[2];
    unsigned int qm = pmask[b*Nn + n];
    for (int m = threadIdx.x; m < EXTm; m += 256) {
        float ax, ay, az; unsigned int km;
        if (m < Nn) {
            const float* pp = pos + (size_t)(b*Nn + m)*3;
            ax = pp[0]; ay = pp[1]; az = pp[2];
            km = pmask[b*Nn + m];
        } else {
            const float* pp = epos + (size_t)(b*Mm + m - Nn)*3;
            ax = pp[0]; ay = pp[1]; az = pp[2];
            km = emask[b*Mm + m - Nn];
        }
        float dx = px - ax, dy = py - ay, dz = pz - az;
        float dist = sqrtf(dx*dx + dy*dy + dz*dz);
        if (qm | km) dist = 1e6f;
        float f = 1.f / (dist + 1.f);
        if (qm) f = 0.f;
        g_pd[(size_t)bn*EXTm + m] = make_float4(dx*f, dy*f, dz*f, 0.f);
    }
}

// ========== bf16-split mma.sync GEMM (R5 core) ==========
#define ST_ROW   40
#define MAT_SZ   (128*ST_ROW*2)
#define STAGE_SZ (4*MAT_SZ)
#define MM_SMEM  (2*STAGE_SZ)

__global__ void __launch_bounds__(256) mm_mma(float* __restrict__ Cout, int mode)
{
    extern __shared__ __align__(16) char smraw[];
    const u32 smBase = smem_u32(smraw);
    const int t = threadIdx.x, wid = t >> 5, lid = t & 31;
    const int wm = wid >> 2, wn = wid & 3;
    const int col0 = blockIdx.x * 128;
    const int row0 = blockIdx.y * 128;
    const int unit = (mode == 0) ? (int)blockIdx.z : mode;
    const int arow0 = (unit == 5) ? (2048 + row0) : row0;

    const __nv_bfloat16* srcs[4] = {
        g_ah + (size_t)arow0*Ee,
        g_al + (size_t)arow0*Ee,
        g_wh + (size_t)unit*Ee*Ee + (size_t)col0*Ee,
        g_wl + (size_t)unit*Ee*Ee + (size_t)col0*Ee
    };

    float acc[4][4][4];
#pragma unroll
    for (int i = 0; i < 4; i++)
#pragma unroll
        for (int j = 0; j < 4; j++)
#pragma unroll
            for (int q = 0; q < 4; q++) acc[i][j][q] = 0.f;

    int cp_mat[8], cp_row[8], cp_q[8];
#pragma unroll
    for (int jj = 0; jj < 8; jj++) {
        int id = t + jj*256;
        cp_mat[jj] = id >> 9; int rem = id & 511;
        cp_row[jj] = rem >> 2; cp_q[jj] = rem & 3;
    }

#define ISSUE(kc, stage)                                                          \
    {   int k0 = (kc)*32;                                                         \
        u32 dB = smBase + (stage)*STAGE_SZ;                                       \
        _Pragma("unroll")                                                         \
        for (int jj = 0; jj < 8; jj++) {                                          \
            const __nv_bfloat16* s = srcs[cp_mat[jj]] + (size_t)cp_row[jj]*Ee + k0 + cp_q[jj]*8; \
            cpasync16(dB + cp_mat[jj]*MAT_SZ + cp_row[jj]*(ST_ROW*2) + cp_q[jj]*16, s); \
        }                                                                         \
        asm volatile("cp.async.commit_group;" ::: "memory");                      \
    }

    ISSUE(0, 0);

    const u32 aoff = (u32)(((lid >> 3) & 1) * 8 + (lid & 7));
    const u32 kbl  = (u32)(((lid >> 4) & 1) * 16);

    for (int kc = 0; kc < 32; kc++) {
        int stage = kc & 1;
        if (kc < 31) ISSUE(kc + 1, stage ^ 1);
        if (kc < 31) asm volatile("cp.async.wait_group 1;" ::: "memory");
        else         asm volatile("cp.async.wait_group 0;" ::: "memory");
        __syncthreads();

        u32 base = smBase + stage*STAGE_SZ;
#pragma unroll
        for (int ks = 0; ks < 2; ks++) {
            u32 kb = kbl + ks*32;
            u32 ah[4][4], al[4][4];
            u32 bh0[4], bh1[4], bl0[4], bl1[4];
#pragma unroll
            for (int im = 0; im < 4; im++) {
                u32 row = (u32)(wm*64 + im*16) + aoff;
                ldsm4(ah[im], base + 0*MAT_SZ + row*(ST_ROW*2) + kb);
                ldsm4(al[im], base + 1*MAT_SZ + row*(ST_ROW*2) + kb);
            }
#pragma unroll
            for (int jn = 0; jn < 2; jn++) {
                u32 row = (u32)(wn*32 + jn*16) + aoff;
                u32 rh[4], rl[4];
                ldsm4(rh, base + 2*MAT_SZ + row*(ST_ROW*2) + kb);
                ldsm4(rl, base + 3*MAT_SZ + row*(ST_ROW*2) + kb);
                bh0[jn*2] = rh[0]; bh1[jn*2] = rh[2]; bh0[jn*2+1] = rh[1]; bh1[jn*2+1] = rh[3];
                bl0[jn*2] = rl[0]; bl1[jn*2] = rl[2]; bl0[jn*2+1] = rl[1]; bl1[jn*2+1] = rl[3];
            }
#pragma unroll
            for (int im = 0; im < 4; im++)
#pragma unroll
                for (int n8 = 0; n8 < 4; n8++) {
                    mma16816(acc[im][n8], ah[im], bh0[n8], bh1[n8]);
                    mma16816(acc[im][n8], al[im], bh0[n8], bh1[n8]);
                    mma16816(acc[im][n8], ah[im], bl0[n8], bl1[n8]);
                }
        }
        __syncthreads();
    }

    const int gid = lid >> 2, tig = lid & 3;
#pragma unroll
    for (int im = 0; im < 4; im++) {
#pragma unroll
        for (int n8 = 0; n8 < 4; n8++) {
            int c = col0 + wn*32 + n8*8 + tig*2;
            int r0 = row0 + wm*64 + im*16 + gid;
            int r1 = r0 + 8;
            float2 v0 = make_float2(acc[im][n8][0], acc[im][n8][1]);
            float2 v1 = make_float2(acc[im][n8][2], acc[im][n8][3]);
            if (unit == 0) {
                v0.x *= SCALING; v0.y *= SCALING; v1.x *= SCALING; v1.y *= SCALING;
                st_hilo(g_qh, g_ql, (size_t)r0*Ee + c, v0);
                st_hilo(g_qh, g_ql, (size_t)r1*Ee + c, v1);
            } else if (unit < 4) {
                __nv_bfloat16 *dh, *dl;
                if (unit == 1) { dh = g_kh; dl = g_kl; }
                else if (unit == 2) { dh = g_vh; dl = g_vl; }
                else { dh = g_veh; dl = g_vel; }
                st_hilo(dh, dl, ((size_t)(r0 >> 8)*EXTm + (r0 & 255))*Ee + c, v0);
                st_hilo(dh, dl, ((size_t)(r1 >> 8)*EXTm + (r1 & 255))*Ee + c, v1);
            } else {
                *(float2*)&Cout[(size_t)r0*Ee + c] = v0;
                *(float2*)&Cout[(size_t)r1*Ee + c] = v1;
            }
        }
    }
}

// ---------------- gather ----------------
__global__ void __launch_bounds__(256) gather_kernel(const int* __restrict__ idx)
{
    int bm = blockIdx.x;
    int b = bm >> 9, m = bm & 511;
    int s = idx[bm];
    size_t so = ((size_t)b*EXTm + s)      * Ee;
    size_t dd = ((size_t)b*EXTm + Nn + m) * Ee;
    int e = threadIdx.x * 4;
    *(uint2*)&g_kh [dd+e] = *(const uint2*)&g_kh [so+e];
    *(uint2*)&g_kl [dd+e] = *(const uint2*)&g_kl [so+e];
    *(uint2*)&g_vh [dd+e] = *(const uint2*)&g_vh [so+e];
    *(uint2*)&g_vl [dd+e] = *(const uint2*)&g_vl [so+e];
    *(uint2*)&g_veh[dd+e] = *(const uint2*)&g_veh[so+e];
    *(uint2*)&g_vel[dd+e] = *(const uint2*)&g_vel[so+e];
}

// ================= tensor-core attention (cp.async pipelined) =================
#define TQ 32
#define SPITCH 776
#define oS  0                  // float S[32][776] = 99328
#define oQ  99328              // Qh/Ql [32][40] (5120)            [phase A]
#define oK  104448             // 2 x (Kh+Kl [64][40]) = 20480     [phase A]
#define oB  124928             // 2 x bias[32][64]f = 16384        [phase A]
#define oW  99328              // Wh/Wl 4ch [32][72] = 36864       [phase B, overlaps Q/K]
#define oV  141312             // 2 x (Vh,Vl,VEh,VEl [64][40]) = 40960 [phase B]
#define oPN 182272             // qmask float[32]
#define oMF 182400             // maskf float[768] (3072)
#define ATTN_SMEM 185472

__global__ void __launch_bounds__(512, 1) attn_mma(
    const float* __restrict__ bias,
    const unsigned char* __restrict__ pmask, const unsigned char* __restrict__ emask)
{
    extern __shared__ __align__(16) char sm[];
    float* S = (float*)(sm + oS);
    float* qmn = (float*)(sm + oPN);
    float* maskf = (float*)(sm + oMF);
    const u32 smb = smem_u32(sm);

    const int t = threadIdx.x, w = t >> 5, lid = t & 31;
    const int nt = blockIdx.x, h = blockIdx.y, b = blockIdx.z;
    const int n0 = nt * TQ;

    const float* biasrow = bias + ((u64)(b*Hh + h)*Nn + n0)*EXTm;

    // ---- init staging ----
    if (t < 256) {
        int r = t >> 3, q = t & 7;
        u64 gi = ((u64)(b*Nn + n0 + r))*Ee + h*32 + q*4;
        *(uint2*)(sm + oQ + r*80 + q*8)        = *(const uint2*)(g_qh + gi);
        *(uint2*)(sm + oQ + 2560 + r*80 + q*8) = *(const uint2*)(g_ql + gi);
    }
    if (t < 32) qmn[t] = pmask[b*Nn + n0 + t] ? 1.f : 0.f;
    for (int i = t; i < EXTm; i += 512) {
        unsigned int mq = (i < Nn) ? pmask[b*Nn + i] : emask[b*Mm + i - Nn];
        maskf[i] = mq ? 1.f : 0.f;
    }

    const u32 aoff = (u32)(((lid >> 3) & 1) * 8 + (lid & 7));
    const u32 acol = (u32)(((lid >> 4) & 1) * 16);

    // cp.async issue of K+bias tile
    const int ka_arr = t >> 8, ka_u = t & 255;
    const int ka_row = ka_u >> 2, ka_q = ka_u & 3;
    const int bb_row = t >> 4, bb_q = t & 15;
#define ISSUE_A(mt, s)                                                                     \
    {   const __nv_bfloat16* ksrc = (ka_arr ? g_kl : g_kh)                                 \
            + ((u64)(b*EXTm + (mt)*64 + ka_row))*Ee + h*32 + ka_q*8;                       \
        cpasync16(smb + oK + (s)*10240 + ka_arr*5120 + ka_row*80 + ka_q*16, ksrc);         \
        const float* bsrc = biasrow + (u64)bb_row*EXTm + (mt)*64 + bb_q*4;                 \
        cpasync16(smb + oB + (s)*8192 + bb_row*256 + bb_q*16, bsrc);                       \
        asm volatile("cp.async.commit_group;" ::: "memory");                               \
    }

    // ---- phase A: S = Q K^T + bias, masked ----
    {
        const int wn = w >> 3, wm8 = w & 7;
        ISSUE_A(0, 0);
        __syncthreads();                     // init staging visible
        for (int mt = 0; mt < 12; mt++) {
            int s = mt & 1;
            asm volatile("cp.async.wait_group 0;" ::: "memory");
            __syncthreads();
            if (mt < 11) ISSUE_A(mt + 1, s ^ 1);
            float c[4] = {0.f, 0.f, 0.f, 0.f};
            u32 kbase = smb + oK + s*10240;
#pragma unroll
            for (int ks = 0; ks < 2; ks++) {
                u32 qa = smb + oQ + (wn*16 + aoff)*80 + acol + ks*32;
                u32 ah[4], al[4];
                ldsm4(ah, qa); ldsm4(al, qa + 2560);
                u32 ka = kbase + (wm8*8 + (lid & 7))*80 + ((lid >> 3) & 1)*16 + ks*32;
                u32 bh[2], bl[2];
                ldsm2(bh, ka); ldsm2(bl, ka + 5120);
                mma16816(c, ah, bh[0], bh[1]);
                mma16816(c, al, bh[0], bh[1]);
                mma16816(c, ah, bl[0], bl[1]);
            }
            int row = wn*16 + (lid >> 2);
            int colL = wm8*8 + (lid & 3)*2;
            int col = mt*64 + colL;
            float* btile = (float*)(sm + oB + s*8192);
            float2 b0 = *(float2*)&btile[row*64 + colL];
            float2 b1 = *(float2*)&btile[(row+8)*64 + colL];
            float qm0 = qmn[row], qm1 = qmn[row+8];
            float m0 = maskf[col], m1 = maskf[col+1];
            c[0] = (qm0 + m0 > 0.f) ? NEGINF : c[0] + b0.x;
            c[1] = (qm0 + m1 > 0.f) ? NEGINF : c[1] + b0.y;
            c[2] = (qm1 + m0 > 0.f) ? NEGINF : c[2] + b1.x;
            c[3] = (qm1 + m1 > 0.f) ? NEGINF : c[3] + b1.y;
            *(float2*)&S[row*SPITCH + col]     = make_float2(c[0], c[1]);
            *(float2*)&S[(row+8)*SPITCH + col] = make_float2(c[2], c[3]);
        }
    }
    __syncthreads();

    // ---- softmax ----
#pragma unroll
    for (int rr = 0; rr < 2; rr++) {
        int ni = w*2 + rr;
        float lm = NEGINF;
#pragma unroll
        for (int i = 0; i < 24; i++) lm = fmaxf(lm, S[ni*SPITCH + lid + i*32]);
#pragma unroll
        for (int o = 16; o; o >>= 1) lm = fmaxf(lm, __shfl_xor_sync(0xffffffffu, lm, o));
        float ls = 0.f;
#pragma unroll
        for (int i = 0; i < 24; i++) {
            float p = __expf(S[ni*SPITCH + lid + i*32] - lm);
            S[ni*SPITCH + lid + i*32] = p;
            ls += p;
        }
#pragma unroll
        for (int o = 16; o; o >>= 1) ls += __shfl_xor_sync(0xffffffffu, ls, o);
        float inv = 1.f / ls;
#pragma unroll
        for (int i = 0; i < 24; i++) S[ni*SPITCH + lid + i*32] *= inv;
    }

    // ---- phase B: 4-channel PV ----
    const int f8 = w & 7;
    const int fn = f8 >> 2, fd = f8 & 3;
    const int ch0 = (w >> 3) * 2;
    float acc[2][4];
#pragma unroll
    for (int cc = 0; cc < 2; cc++)
#pragma unroll
        for (int q = 0; q < 4; q++) acc[cc][q] = 0.f;

    const float4* pdg = g_pd + (u64)(b*Nn + n0)*EXTm;
    const int pd_ni0 = t >> 5,          pd_ml0 = (t & 31)*2;
    const int pd_ni1 = (t + 512) >> 5,  pd_ml1 = ((t + 512) & 31)*2;

#define ISSUE_V(mt, s)                                                                      \
    {   _Pragma("unroll")                                                                   \
        for (int jj = 0; jj < 2; jj++) {                                                    \
            int id = t + jj*512;                                                            \
            int arr = id >> 8, u = id & 255;                                                \
            int row = u >> 2, q = u & 3;                                                    \
            const __nv_bfloat16* src = ((arr==0)?g_vh:(arr==1)?g_vl:(arr==2)?g_veh:g_vel)   \
                + ((u64)(b*EXTm + (mt)*64 + row))*Ee + h*32 + q*8;                          \
            cpasync16(smb + oV + (s)*20480 + arr*5120 + row*80 + q*16, src);                \
        }                                                                                   \
        asm volatile("cp.async.commit_group;" ::: "memory");                                \
    }

    float4 pc00, pc01, pc10, pc11;       // current-tile pd regs
    ISSUE_V(0, 0);
    pc00 = pdg[(u64)pd_ni0*EXTm + 0*64 + pd_ml0];
    pc01 = pdg[(u64)pd_ni0*EXTm + 0*64 + pd_ml0 + 1];
    pc10 = pdg[(u64)pd_ni1*EXTm + 0*64 + pd_ml1];
    pc11 = pdg[(u64)pd_ni1*EXTm + 0*64 + pd_ml1 + 1];

    for (int mt = 0; mt < 12; mt++) {
        int s = mt & 1;
        asm volatile("cp.async.wait_group 0;" ::: "memory");
        __syncthreads();                  // V[s] ready; prev mma done with W
        // weight build
#pragma unroll
        for (int jj = 0; jj < 2; jj++) {
            int ni = jj ? pd_ni1 : pd_ni0;
            int ml = jj ? pd_ml1 : pd_ml0;
            float4 d0 = jj ? pc10 : pc00;
            float4 d1 = jj ? pc11 : pc01;
            float2 pp = *(float2*)&S[ni*SPITCH + mt*64 + ml];
            float wsa[4] = { pp.x, pp.x*d0.x, pp.x*d0.y, pp.x*d0.z };
            float wsb[4] = { pp.y, pp.y*d1.x, pp.y*d1.y, pp.y*d1.z };
#pragma unroll
            for (int c = 0; c < 4; c++) {
                __nv_bfloat16 ha = __float2bfloat16(wsa[c]);
                __nv_bfloat16 hb = __float2bfloat16(wsb[c]);
                __nv_bfloat16 la = __float2bfloat16(wsa[c] - __bfloat162float(ha));
                __nv_bfloat16 lb = __float2bfloat16(wsb[c] - __bfloat162float(hb));
                *(__nv_bfloat162*)(sm + oW + c*4608 + ni*144 + ml*2)         = __halves2bfloat162(ha, hb);
                *(__nv_bfloat162*)(sm + oW + 18432 + c*4608 + ni*144 + ml*2) = __halves2bfloat162(la, lb);
            }
        }
        if (mt < 11) {
            ISSUE_V(mt + 1, s ^ 1);
            pc00 = pdg[(u64)pd_ni0*EXTm + (mt+1)*64 + pd_ml0];
            pc01 = pdg[(u64)pd_ni0*EXTm + (mt+1)*64 + pd_ml0 + 1];
            pc10 = pdg[(u64)pd_ni1*EXTm + (mt+1)*64 + pd_ml1];
            pc11 = pdg[(u64)pd_ni1*EXTm + (mt+1)*64 + pd_ml1 + 1];
        }
        __syncthreads();
        u32 vbase = smb + oV + s*20480;
#pragma unroll
        for (int ks = 0; ks < 4; ks++) {
            u32 vrow = (u32)(ks*16 + (lid & 15));
#pragma unroll
            for (int cc = 0; cc < 2; cc++) {
                int c = ch0 + cc;
                u32 varr = (c == 0) ? 2u : 0u;
                u32 va = vbase + varr*5120 + vrow*80 + fd*16;
                u32 bh[2], bl[2];
                ldsm2t(bh, va);
                ldsm2t(bl, va + 5120);
                u32 wa = smb + oW + c*4608 + (fn*16 + aoff)*144 + acol + ks*32;
                u32 ah[4], al[4];
                ldsm4(ah, wa); ldsm4(al, wa + 18432);
                mma16816(acc[cc], ah, bh[0], bh[1]);
                mma16816(acc[cc], al, bh[0], bh[1]);
                mma16816(acc[cc], ah, bl[0], bl[1]);
            }
        }
    }

    // ---- epilogue: write bf16 hi/lo directly into out-GEMM A buffers ----
    {
        int gid = lid >> 2, tig = lid & 3;
        int col = h*32 + fd*8 + tig*2;
#pragma unroll
        for (int cc = 0; cc < 2; cc++) {
            int c = ch0 + cc;
            int r0 = n0 + fn*16 + gid;
            int r1 = r0 + 8;
            float2 v0 = make_float2(acc[cc][0], acc[cc][1]);
            float2 v1 = make_float2(acc[cc][2], acc[cc][3]);
            u64 row0g, row1g;
            if (c == 0) {
                row0g = (u64)(b*Nn + r0);
                row1g = (u64)(b*Nn + r1);
            } else {
                row0g = 2048 + ((u64)(b*Nn + r0)*3 + (c-1));
                row1g = 2048 + ((u64)(b*Nn + r1)*3 + (c-1));
            }
            st_hilo(g_ah, g_al, row0g*Ee + col, v0);
            st_hilo(g_ah, g_al, row1g*Ee + col, v1);
        }
    }
}

// ---------------- host entry ----------------
extern "C" void kernel_launch(void* const* d_in, const int* in_sizes, int n_in,
                              void* d_out, int out_size)
{
    const float* x    = (const float*)d_in[0];
    const float* pos  = (const float*)d_in[1];
    const float* epos = (const float*)d_in[2];
    const float* bias = (const float*)d_in[3];
    const unsigned char* pmask = (const unsigned char*)d_in[4];
    const unsigned char* emask = (const unsigned char*)d_in[5];
    const int*   idx  = (const int*)d_in[6];
    const float* Wq   = (const float*)d_in[7];
    const float* Wk   = (const float*)d_in[8];
    const float* Wv   = (const float*)d_in[9];
    const float* Wve  = (const float*)d_in[10];
    const float* Wo   = (const float*)d_in[11];
    const float* Woe  = (const float*)d_in[12];
    float* out = (float*)d_out;

    cudaFuncSetAttribute(mm_mma, cudaFuncAttributeMaxDynamicSharedMemorySize, MM_SMEM);
    cudaFuncSetAttribute(attn_mma, cudaFuncAttributeMaxDynamicSharedMemorySize, ATTN_SMEM);

    geom_kernel<<<Bb*Nn, 256>>>(pos, epos, pmask, emask);
    cvt_w<<<dim3(1024, 6), 256>>>(Wq, Wk, Wv, Wve, Woe, Wo);
    cvt_x<<<2048, 256>>>(x);

    mm_mma<<<dim3(8, 16, 4), 256, MM_SMEM>>>(nullptr, 0);    // q,k,v,ve projections

    gather_kernel<<<Bb*Mm, 256>>>(idx);

    attn_mma<<<dim3(8, 32, 8), 512, ATTN_SMEM>>>(bias, pmask, emask);

    mm_mma<<<dim3(8, 16, 1), 256, MM_SMEM>>>(out, 4);                       // xo @ Woe^T
    mm_mma<<<dim3(8, 48, 1), 256, MM_SMEM>>>(out + (size_t)2048*Ee, 5);     // vec @ Wo^T
}